// round 11
// baseline (speedup 1.0000x reference)
#include <cuda_runtime.h>
#include <cuda_fp16.h>
#include <math.h>
#include <stdint.h>

#define BATCH 4
#define SEQ   2048
#define DIM   1024
#define NH    16
#define HD    64
#define MROWS (BATCH*SEQ)

// ---------------------------------------------------------------------------
// Scratch (__device__ globals; allocation-free rule)
// ---------------------------------------------------------------------------
__device__ float g_Q[BATCH*NH*SEQ*HD];
__device__ float g_K[BATCH*NH*SEQ*HD];
__device__ float g_V[BATCH*NH*SEQ*HD];
// fp16x2 GEMM operands: A2 = [Xhi | Xlo] (row width 2048), B = fp16 weights
__device__ __half g_A2[(size_t)MROWS*2048];
__device__ __half g_B2[(size_t)DIM*DIM];
__device__ __half g_B2o[(size_t)DIM*DIM];
// fp16 hi/lo planes for attention (RoPE + scale pre-applied to Q/K)
__device__ __half g_Qh[BATCH*NH*SEQ*HD];
__device__ __half g_Ql[BATCH*NH*SEQ*HD];
__device__ __half g_Kh[BATCH*NH*SEQ*HD];
__device__ __half g_Kl[BATCH*NH*SEQ*HD];
__device__ __half g_Vh[BATCH*NH*SEQ*HD];
__device__ __half g_Vl[BATCH*NH*SEQ*HD];

__device__ __forceinline__ uint32_t smem_u32(const void* p) {
    uint32_t a;
    asm("{ .reg .u64 t; cvta.to.shared.u64 t, %1; cvt.u32.u64 %0, t; }" : "=r"(a) : "l"(p));
    return a;
}

#define LDMATRIX_X4(r0, r1, r2, r3, addr) \
    asm volatile("ldmatrix.sync.aligned.m8n8.x4.shared.b16 {%0,%1,%2,%3}, [%4];" \
        : "=r"(r0), "=r"(r1), "=r"(r2), "=r"(r3) : "r"(addr))

#define LDMATRIX_X4T(r0, r1, r2, r3, addr) \
    asm volatile("ldmatrix.sync.aligned.m8n8.x4.trans.shared.b16 {%0,%1,%2,%3}, [%4];" \
        : "=r"(r0), "=r"(r1), "=r"(r2), "=r"(r3) : "r"(addr))

#define MMA_F16(c, a, b0v, b1v) \
    asm volatile("mma.sync.aligned.m16n8k16.row.col.f32.f16.f16.f32 " \
        "{%0,%1,%2,%3}, {%4,%5,%6,%7}, {%8,%9}, {%0,%1,%2,%3};" \
        : "+f"((c)[0]), "+f"((c)[1]), "+f"((c)[2]), "+f"((c)[3]) \
        : "r"((a)[0]), "r"((a)[1]), "r"((a)[2]), "r"((a)[3]), "r"(b0v), "r"(b1v))

#define CP_ASYNC16(dst, src) \
    asm volatile("cp.async.cg.shared.global [%0], [%1], 16;" :: "r"(dst), "l"(src))
#define CP_COMMIT() asm volatile("cp.async.commit_group;" ::: "memory")
#define CP_WAIT0()  asm volatile("cp.async.wait_group 0;" ::: "memory")
#define CP_WAIT1()  asm volatile("cp.async.wait_group 1;" ::: "memory")

__device__ __forceinline__ uint32_t h2u(__half2 h) { return *reinterpret_cast<uint32_t*>(&h); }
__device__ __forceinline__ float ex2f(float x) {
    float y; asm("ex2.approx.f32 %0, %1;" : "=f"(y) : "f"(x)); return y;
}

struct h4 { __half2 a, b; };

// ---------------------------------------------------------------------------
// X split: f32 -> fp16 hi/lo into g_A2 (row 2048: [hi(1024) | lo(1024)])
// ---------------------------------------------------------------------------
__global__ void split_x(const float* __restrict__ in)
{
    int i = blockIdx.x * blockDim.x + threadIdx.x;   // float4 index
    if (i >= MROWS * 256) return;
    int r = i >> 8, c4 = i & 255;
    float4 v = ((const float4*)in)[i];
    __half2 h01 = __floats2half2_rn(v.x, v.y);
    __half2 h23 = __floats2half2_rn(v.z, v.w);
    __half2 l01 = __floats2half2_rn(v.x - __half2float(__low2half(h01)),
                                    v.y - __half2float(__high2half(h01)));
    __half2 l23 = __floats2half2_rn(v.z - __half2float(__low2half(h23)),
                                    v.w - __half2float(__high2half(h23)));
    size_t base = (size_t)r * 2048 + c4 * 4;
    h4 hv; hv.a = h01; hv.b = h23;
    h4 lv; lv.a = l01; lv.b = l23;
    *(h4*)(g_A2 + base)        = hv;
    *(h4*)(g_A2 + base + 1024) = lv;
}

// ---------------------------------------------------------------------------
// W convert: f32 -> fp16 (row 1024). which: 0 -> g_B2, 1 -> g_B2o
// ---------------------------------------------------------------------------
__global__ void split_w(const float* __restrict__ in, int which)
{
    int i = blockIdx.x * blockDim.x + threadIdx.x;   // float4 index
    if (i >= DIM * 256) return;
    float4 v = ((const float4*)in)[i];
    h4 hv;
    hv.a = __floats2half2_rn(v.x, v.y);
    hv.b = __floats2half2_rn(v.z, v.w);
    __half* out = which ? g_B2o : g_B2;
    *(h4*)(out + (size_t)i * 4) = hv;
}

// ---------------------------------------------------------------------------
// mma.sync fp16x2 GEMM (unchanged, 130us measured)
// ---------------------------------------------------------------------------
#define NST      32
#define STAGE_B  (128*144)
#define GEMM_SMEM (4*STAGE_B)            // 73728

__global__ __launch_bounds__(256)
void gemm_mma(const float* __restrict__ bias, float* __restrict__ dst_param,
              int mode, int bsel)
{
    extern __shared__ __align__(16) char sm[];
    uint32_t sb = smem_u32(sm);

    const __half* Bmat = bsel ? g_B2o : g_B2;

    int tid  = threadIdx.x;
    int lane = tid & 31;
    int wid  = tid >> 5;
    int wm   = wid & 1;
    int wn   = wid >> 1;
    int m0 = blockIdx.y << 7, n0 = blockIdx.x << 7;

    int lr = ((lane >> 3) & 1) * 8 + (lane & 7);
    int lk = (lane >> 4) * 8;

    float c[4][4][4];
    #pragma unroll
    for (int mf = 0; mf < 4; mf++)
        #pragma unroll
        for (int nf = 0; nf < 4; nf++)
            #pragma unroll
            for (int v = 0; v < 4; v++) c[mf][nf][v] = 0.0f;

    auto load_stage = [&](int t, int buf) {
        int kp = t << 6;
        int bc = kp & 1023;
        const __half* Ab = g_A2 + (size_t)m0 * 2048 + kp;
        const __half* Bb = Bmat + (size_t)n0 * 1024 + bc;
        uint32_t sa  = sb + buf * STAGE_B;
        uint32_t sbb = sb + 2 * STAGE_B + buf * STAGE_B;
        #pragma unroll
        for (int it = 0; it < 4; it++) {
            int id = tid + (it << 8);
            int r = id >> 3, ch = id & 7;
            CP_ASYNC16(sa  + r * 144 + (ch << 4), Ab + (size_t)r * 2048 + (ch << 3));
            CP_ASYNC16(sbb + r * 144 + (ch << 4), Bb + (size_t)r * 1024 + (ch << 3));
        }
        CP_COMMIT();
    };

    load_stage(0, 0);

    #pragma unroll 1
    for (int t = 0; t < NST; t++) {
        CP_WAIT0();
        __syncthreads();
        if (t + 1 < NST) load_stage(t + 1, (t + 1) & 1);

        uint32_t sa  = sb + (t & 1) * STAGE_B;
        uint32_t sbb = sb + 2 * STAGE_B + (t & 1) * STAGE_B;

        #pragma unroll
        for (int kk = 0; kk < 64; kk += 16) {
            uint32_t a[4][4];
            #pragma unroll
            for (int mf = 0; mf < 4; mf++) {
                uint32_t ad = sa + (uint32_t)(wm * 64 + mf * 16 + lr) * 144 + (kk + lk) * 2;
                LDMATRIX_X4(a[mf][0], a[mf][1], a[mf][2], a[mf][3], ad);
            }
            uint32_t b[2][4];
            #pragma unroll
            for (int nb = 0; nb < 2; nb++) {
                uint32_t bd = sbb + (uint32_t)(wn * 32 + nb * 16 + lr) * 144 + (kk + lk) * 2;
                LDMATRIX_X4(b[nb][0], b[nb][1], b[nb][2], b[nb][3], bd);
            }
            #pragma unroll
            for (int mf = 0; mf < 4; mf++) {
                #pragma unroll
                for (int nf = 0; nf < 4; nf++) {
                    int nb = nf >> 1;
                    uint32_t b0 = (nf & 1) ? b[nb][1] : b[nb][0];
                    uint32_t b1 = (nf & 1) ? b[nb][3] : b[nb][2];
                    MMA_F16(c[mf][nf], a[mf], b0, b1);
                }
            }
        }
        __syncthreads();
    }

    int rq = lane >> 2, cq = (lane & 3) * 2;
    float2 bv[4];
    #pragma unroll
    for (int nf = 0; nf < 4; nf++) {
        int col = n0 + wn * 32 + nf * 8 + cq;
        bv[nf] = make_float2(bias[col], bias[col + 1]);
    }

    #pragma unroll
    for (int mf = 0; mf < 4; mf++) {
        #pragma unroll
        for (int nf = 0; nf < 4; nf++) {
            int r   = m0 + wm * 64 + mf * 16 + rq;
            int col = n0 + wn * 32 + nf * 8 + cq;
            float2 lo = make_float2(c[mf][nf][0] + bv[nf].x, c[mf][nf][1] + bv[nf].y);
            float2 hi = make_float2(c[mf][nf][2] + bv[nf].x, c[mf][nf][3] + bv[nf].y);
            if (mode == 3) {
                *(float2*)(dst_param + (size_t)r * 1024 + col)       = lo;
                *(float2*)(dst_param + (size_t)(r + 8) * 1024 + col) = hi;
            } else {
                float* g = (mode == 0) ? g_Q : (mode == 1) ? g_K : g_V;
                int h = col >> 6, d0 = col & 63;
                int b1 = r >> 11, s1 = r & 2047;
                *(float2*)(g + (((size_t)(b1 * NH + h) * SEQ + s1) << 6) + d0) = lo;
                int s2 = (r + 8) & 2047;
                *(float2*)(g + (((size_t)(b1 * NH + h) * SEQ + s2) << 6) + d0) = hi;
            }
        }
    }
}

// ---------------------------------------------------------------------------
// Fused RoPE + fp16 hi/lo conversion.
// ---------------------------------------------------------------------------
#define QSCALE 0.18033688011112042f   // 0.125 * log2(e)

__global__ void conv_rope()
{
    int gw   = (blockIdx.x * blockDim.x + threadIdx.x) >> 5;
    int lane = threadIdx.x & 31;
    int which = blockIdx.y;
    const float* src = (which == 0) ? g_Q : (which == 1) ? g_K : g_V;
    __half* dh = (which == 0) ? g_Qh : (which == 1) ? g_Kh : g_Vh;
    __half* dl = (which == 0) ? g_Ql : (which == 1) ? g_Kl : g_Vl;
    int s = gw & (SEQ - 1);
    const float* row = src + (size_t)gw * HD;

    float v0, v1;
    if (which < 2) {
        float invf = (float)pow(10000.0, -(double)lane / 32.0);
        float sn, cs;
        sincosf((float)s * invf, &sn, &cs);
        float xe   = row[lane];
        float xe32 = row[lane + 32];
        float x2e  = row[2 * lane];
        float x2e1 = row[2 * lane + 1];
        v0 = xe   * cs - x2e1 * sn;
        v1 = xe32 * cs + x2e  * sn;
        if (which == 0) { v0 *= QSCALE; v1 *= QSCALE; }
    } else {
        v0 = row[lane];
        v1 = row[lane + 32];
    }
    __half h0 = __float2half_rn(v0);
    __half h1 = __float2half_rn(v1);
    size_t o = (size_t)gw * HD;
    dh[o + lane]      = h0;
    dh[o + lane + 32] = h1;
    dl[o + lane]      = __float2half_rn(v0 - __half2float(h0));
    dl[o + lane + 32] = __float2half_rn(v1 - __half2float(h1));
}

// ---------------------------------------------------------------------------
// Flash attention R11: BM=128 (8 warps), BN=64.
//  - Q kept in persistent SMEM (hi/lo planes); fragments reloaded per kc.
//    Frees ~32 regs/thread so __launch_bounds__(256,2) fits WITHOUT spills
//    -> 2 CTAs/SM (R7-R10 ran at 1 CTA/SM: >128 regs uncapped).
//  - f32 ex2 + f16x2 pack (R10's ex2.approx.f16x2 cost 3e-4 rel_err).
//  - ones-MMA row sums retained.
// SMEM: Qhi 18432 | Qlo 18432 | KV stage0 36864 | KV stage1 36864 = 110592.
// ---------------------------------------------------------------------------
#define ROWB 144
#define QSM  18432               // one 128-row Q plane
#define PLANE (64*ROWB)          // 9216 (one 64-row KV plane)
#define KVST (4*PLANE)           // 36864 per KV stage
#define ATTN_SMEM (2*QSM + 2*KVST)   // 110592

__global__ __launch_bounds__(256, 2)
void attn_mma()
{
    extern __shared__ __align__(16) char smb[];
    uint32_t sb = smem_u32(smb);

    int tid  = threadIdx.x;
    int lane = tid & 31;
    int wid  = tid >> 5;                    // 0..7
    int bh   = blockIdx.y;
    int bx   = gridDim.x - 1 - blockIdx.x;  // heaviest CTAs first
    int q0   = bx << 7;
    int nt   = 2 * bx + 2;

    const __half* Kh = g_Kh + (size_t)bh * SEQ * HD;
    const __half* Kl = g_Kl + (size_t)bh * SEQ * HD;
    const __half* Vh = g_Vh + (size_t)bh * SEQ * HD;
    const __half* Vl = g_Vl + (size_t)bh * SEQ * HD;

    int lr = ((lane >> 3) & 1) * 8 + (lane & 7);
    int lk = (lane >> 4) * 8;
    int rq = lane >> 2, cq = (lane & 3) * 2;

    auto load_kv = [&](int t, int stage) {
        int k0 = t << 6;
        uint32_t base = sb + 2*QSM + stage * KVST;
        #pragma unroll
        for (int it = 0; it < 2; it++) {
            int id = tid + (it << 8);
            int r = id >> 3, ch = id & 7;
            uint32_t o = r * ROWB + (ch << 4);
            int go = ((k0 + r) << 6) + (ch << 3);
            CP_ASYNC16(base + o,             Kh + go);
            CP_ASYNC16(base + PLANE + o,     Kl + go);
            CP_ASYNC16(base + 2*PLANE + o,   Vh + go);
            CP_ASYNC16(base + 3*PLANE + o,   Vl + go);
        }
        CP_COMMIT();
    };

    // prologue: Q hi/lo into persistent planes (2 planes x 128 rows x 8 chunks)
    {
        const __half* Qh = g_Qh + (size_t)bh * SEQ * HD;
        const __half* Ql = g_Ql + (size_t)bh * SEQ * HD;
        #pragma unroll
        for (int it = 0; it < 8; it++) {
            int id = tid + (it << 8);          // 0..2047
            int pl = id >> 10;                 // 0=hi, 1=lo
            int rem = id & 1023;
            int r = rem >> 3, ch = rem & 7;
            uint32_t o = pl * QSM + r * ROWB + (ch << 4);
            const __half* src = pl ? Ql : Qh;
            CP_ASYNC16(sb + o, src + ((q0 + r) << 6) + (ch << 3));
        }
        CP_COMMIT();
    }
    load_kv(0, 0);

    float acc[8][4];
    #pragma unroll
    for (int nf = 0; nf < 8; nf++)
        #pragma unroll
        for (int v = 0; v < 4; v++) acc[nf][v] = 0.0f;
    float lacc[4] = {0.0f, 0.0f, 0.0f, 0.0f};   // ones-MMA row sums
    float m_i[2] = {-1e30f, -1e30f};

    int wminrow = q0 + wid*16;

    CP_WAIT0();
    __syncthreads();

    #pragma unroll 1
    for (int t = 0; t < nt; t++) {
        int k0 = t << 6;
        if (t + 1 < nt) { load_kv(t + 1, (t + 1) & 1); CP_WAIT1(); }
        // (CP_WAIT1 keeps current stage complete; last tile already complete)
        __syncthreads();

        uint32_t khb = sb + 2*QSM + (t & 1) * KVST;
        uint32_t klb = khb + PLANE;
        uint32_t vhb = khb + 2*PLANE;
        uint32_t vlb = khb + 3*PLANE;

        // ---- S = Q K^T (3-term hi/lo), Q fragments reloaded per kc ----
        float sc[8][4];
        #pragma unroll
        for (int nf = 0; nf < 8; nf++)
            #pragma unroll
            for (int v = 0; v < 4; v++) sc[nf][v] = 0.0f;

        #pragma unroll
        for (int kc = 0; kc < 4; kc++) {
            uint32_t qoff = (uint32_t)(wid*16 + lr) * ROWB + (kc*16 + lk) * 2;
            uint32_t qh[4], ql[4];
            LDMATRIX_X4(qh[0], qh[1], qh[2], qh[3], sb + qoff);
            LDMATRIX_X4(ql[0], ql[1], ql[2], ql[3], sb + QSM + qoff);
            #pragma unroll
            for (int nb = 0; nb < 4; nb++) {
                uint32_t off = (uint32_t)(nb*16 + lr) * ROWB + (kc*16 + lk) * 2;
                uint32_t bh0, bh1, bh2, bh3, bl0, bl1, bl2, bl3;
                LDMATRIX_X4(bh0, bh1, bh2, bh3, khb + off);
                LDMATRIX_X4(bl0, bl1, bl2, bl3, klb + off);
                MMA_F16(sc[2*nb],   qh, bh0, bh2);
                MMA_F16(sc[2*nb],   ql, bh0, bh2);
                MMA_F16(sc[2*nb],   qh, bl0, bl2);
                MMA_F16(sc[2*nb+1], qh, bh1, bh3);
                MMA_F16(sc[2*nb+1], ql, bh1, bh3);
                MMA_F16(sc[2*nb+1], qh, bl1, bl3);
            }
        }

        // ---- causal mask ----
        if (k0 + 63 > wminrow) {
            int row0 = wminrow + rq;
            #pragma unroll
            for (int nf = 0; nf < 8; nf++) {
                int col = k0 + nf*8 + cq;
                if (col     > row0)     sc[nf][0] = -1e30f;
                if (col + 1 > row0)     sc[nf][1] = -1e30f;
                if (col     > row0 + 8) sc[nf][2] = -1e30f;
                if (col + 1 > row0 + 8) sc[nf][3] = -1e30f;
            }
        }

        // ---- online softmax: f32 ex2, pack to f16x2 ----
        uint32_t pr[8][2];
        #pragma unroll
        for (int i = 0; i < 2; i++) {
            float mx = -1e30f;
            #pragma unroll
            for (int nf = 0; nf < 8; nf++)
                mx = fmaxf(mx, fmaxf(sc[nf][2*i], sc[nf][2*i+1]));
            mx = fmaxf(mx, __shfl_xor_sync(0xffffffffu, mx, 1));
            mx = fmaxf(mx, __shfl_xor_sync(0xffffffffu, mx, 2));
            float mnew  = fmaxf(m_i[i], mx);
            float scale = ex2f(m_i[i] - mnew);
            float neg   = -mnew;
            #pragma unroll
            for (int nf = 0; nf < 8; nf++) {
                float p0 = ex2f(sc[nf][2*i]   + neg);
                float p1 = ex2f(sc[nf][2*i+1] + neg);
                asm("cvt.rn.f16x2.f32 %0, %1, %2;" : "=r"(pr[nf][i]) : "f"(p1), "f"(p0));
            }
            m_i[i] = mnew;
            lacc[2*i]   *= scale;
            lacc[2*i+1] *= scale;
            #pragma unroll
            for (int nf = 0; nf < 8; nf++) {
                acc[nf][2*i]   *= scale;
                acc[nf][2*i+1] *= scale;
            }
        }

        // ---- ctx += P * (Vhi + Vlo); row sums via ones-MMA ----
        #pragma unroll
        for (int kc = 0; kc < 4; kc++) {
            uint32_t ph[4] = { pr[2*kc][0], pr[2*kc][1], pr[2*kc+1][0], pr[2*kc+1][1] };
            MMA_F16(lacc, ph, 0x3C003C00u, 0x3C003C00u);
            #pragma unroll
            for (int db = 0; db < 4; db++) {
                uint32_t off = (uint32_t)(kc*16 + (lane & 15)) * ROWB
                             + (db*16 + ((lane >> 4) << 3)) * 2;
                uint32_t vh0, vh1, vh2, vh3, vl0, vl1, vl2, vl3;
                LDMATRIX_X4T(vh0, vh1, vh2, vh3, vhb + off);
                LDMATRIX_X4T(vl0, vl1, vl2, vl3, vlb + off);
                MMA_F16(acc[2*db],   ph, vh0, vh1);
                MMA_F16(acc[2*db],   ph, vl0, vl1);
                MMA_F16(acc[2*db+1], ph, vh2, vh3);
                MMA_F16(acc[2*db+1], ph, vl2, vl3);
            }
        }
        __syncthreads();
    }

    // ---- epilogue: normalize + fp16 hi/lo split straight into g_A2 ----
    int b = bh >> 4, h = bh & 15;
    #pragma unroll
    for (int i = 0; i < 2; i++) {
        float inv = 1.0f / lacc[2*i];
        int s = q0 + wid*16 + rq + 8*i;
        __half* rowp = g_A2 + ((size_t)(b * SEQ + s) << 11) + (h << 6);
        #pragma unroll
        for (int nf = 0; nf < 8; nf++) {
            float v0 = acc[nf][2*i]   * inv;
            float v1 = acc[nf][2*i+1] * inv;
            __half2 hv = __floats2half2_rn(v0, v1);
            __half2 lv = __floats2half2_rn(v0 - __half2float(__low2half(hv)),
                                           v1 - __half2float(__high2half(hv)));
            *(__half2*)(rowp + nf*8 + cq)        = hv;
            *(__half2*)(rowp + 1024 + nf*8 + cq) = lv;
        }
    }
}

// ---------------------------------------------------------------------------
extern "C" void kernel_launch(void* const* d_in, const int* in_sizes, int n_in,
                              void* d_out, int out_size)
{
    const float* query = (const float*)d_in[0];
    const float* key   = (const float*)d_in[1];
    const float* value = (const float*)d_in[2];
    const float* w_q = (const float*)d_in[4];
    const float* b_q = (const float*)d_in[5];
    const float* w_k = (const float*)d_in[6];
    const float* b_k = (const float*)d_in[7];
    const float* w_v = (const float*)d_in[8];
    const float* b_v = (const float*)d_in[9];
    const float* w_o = (const float*)d_in[10];
    const float* b_o = (const float*)d_in[11];
    float* out = (float*)d_out;

    static int attr_set = 0;
    if (!attr_set) {
        cudaFuncSetAttribute(gemm_mma, cudaFuncAttributeMaxDynamicSharedMemorySize, GEMM_SMEM);
        cudaFuncSetAttribute(attn_mma, cudaFuncAttributeMaxDynamicSharedMemorySize, ATTN_SMEM);
        attr_set = 1;
    }

    dim3 ggrid(DIM / 128, MROWS / 128);   // (8, 64)

    split_x<<<MROWS, 256>>>(query);                 // 0
    split_w<<<DIM,   256>>>(w_q, 0);                // 1
    split_w<<<DIM,   256>>>(w_o, 1);                // 2
    gemm_mma<<<ggrid, 256, GEMM_SMEM>>>(b_q, nullptr, 0, 0);  // 3 <- profiled

    split_x<<<MROWS, 256>>>(key);                   // 4
    split_w<<<DIM,   256>>>(w_k, 0);                // 5
    gemm_mma<<<ggrid, 256, GEMM_SMEM>>>(b_k, nullptr, 1, 0);  // 6

    split_x<<<MROWS, 256>>>(value);                 // 7
    split_w<<<DIM,   256>>>(w_v, 0);                // 8
    gemm_mma<<<ggrid, 256, GEMM_SMEM>>>(b_v, nullptr, 2, 0);  // 9

    conv_rope<<<dim3(BATCH*NH*SEQ/8, 3), 256>>>();  // 10
    attn_mma<<<dim3(SEQ/128, BATCH*NH), 256, ATTN_SMEM>>>();  // 11

    gemm_mma<<<ggrid, 256, GEMM_SMEM>>>(b_o, out, 3, 1);      // 12
}

// round 12
// speedup vs baseline: 2.3081x; 2.3081x over previous
#include <cuda_runtime.h>
#include <cuda_fp16.h>
#include <math.h>
#include <stdint.h>

#define BATCH 4
#define SEQ   2048
#define DIM   1024
#define NH    16
#define HD    64
#define MROWS (BATCH*SEQ)

// ---------------------------------------------------------------------------
// Scratch (__device__ globals; allocation-free rule)
// ---------------------------------------------------------------------------
__device__ float g_Q[BATCH*NH*SEQ*HD];
__device__ float g_K[BATCH*NH*SEQ*HD];
__device__ float g_V[BATCH*NH*SEQ*HD];
// fp16x2 GEMM operands: A2 = [Xhi | Xlo] (row width 2048), B = fp16 weights
__device__ __half g_A2[(size_t)MROWS*2048];
__device__ __half g_B2[(size_t)DIM*DIM];
__device__ __half g_B2o[(size_t)DIM*DIM];
// fp16 hi/lo planes for attention (RoPE + scale pre-applied to Q/K)
__device__ __half g_Qh[BATCH*NH*SEQ*HD];
__device__ __half g_Ql[BATCH*NH*SEQ*HD];
__device__ __half g_Kh[BATCH*NH*SEQ*HD];
__device__ __half g_Kl[BATCH*NH*SEQ*HD];
__device__ __half g_Vh[BATCH*NH*SEQ*HD];
__device__ __half g_Vl[BATCH*NH*SEQ*HD];
// RoPE tables: cos/sin of s * 10000^(-lane/32), f32, [SEQ][32]
__device__ float g_costab[SEQ*32];
__device__ float g_sintab[SEQ*32];

__device__ __forceinline__ uint32_t smem_u32(const void* p) {
    uint32_t a;
    asm("{ .reg .u64 t; cvta.to.shared.u64 t, %1; cvt.u32.u64 %0, t; }" : "=r"(a) : "l"(p));
    return a;
}

#define LDMATRIX_X4(r0, r1, r2, r3, addr) \
    asm volatile("ldmatrix.sync.aligned.m8n8.x4.shared.b16 {%0,%1,%2,%3}, [%4];" \
        : "=r"(r0), "=r"(r1), "=r"(r2), "=r"(r3) : "r"(addr))

#define LDMATRIX_X4T(r0, r1, r2, r3, addr) \
    asm volatile("ldmatrix.sync.aligned.m8n8.x4.trans.shared.b16 {%0,%1,%2,%3}, [%4];" \
        : "=r"(r0), "=r"(r1), "=r"(r2), "=r"(r3) : "r"(addr))

#define MMA_F16(c, a, b0v, b1v) \
    asm volatile("mma.sync.aligned.m16n8k16.row.col.f32.f16.f16.f32 " \
        "{%0,%1,%2,%3}, {%4,%5,%6,%7}, {%8,%9}, {%0,%1,%2,%3};" \
        : "+f"((c)[0]), "+f"((c)[1]), "+f"((c)[2]), "+f"((c)[3]) \
        : "r"((a)[0]), "r"((a)[1]), "r"((a)[2]), "r"((a)[3]), "r"(b0v), "r"(b1v))

#define CP_ASYNC16(dst, src) \
    asm volatile("cp.async.cg.shared.global [%0], [%1], 16;" :: "r"(dst), "l"(src))
#define CP_COMMIT() asm volatile("cp.async.commit_group;" ::: "memory")
#define CP_WAIT0()  asm volatile("cp.async.wait_group 0;" ::: "memory")
#define CP_WAIT1()  asm volatile("cp.async.wait_group 1;" ::: "memory")

__device__ __forceinline__ uint32_t h2u(__half2 h) { return *reinterpret_cast<uint32_t*>(&h); }
__device__ __forceinline__ float ex2f(float x) {
    float y; asm("ex2.approx.f32 %0, %1;" : "=f"(y) : "f"(x)); return y;
}

struct h4 { __half2 a, b; };

// ---------------------------------------------------------------------------
// RoPE table init: ONE pow/sincos per distinct (s, lane) pair (65536 total),
// bit-identical to the old per-thread computation (which redundantly did
// 8.4M double-precision pow calls on a chip with gutted FP64 throughput).
// ---------------------------------------------------------------------------
__global__ void init_tbl()
{
    int idx = blockIdx.x * blockDim.x + threadIdx.x;   // s*32 + lane
    if (idx >= SEQ * 32) return;
    int lane = idx & 31;
    int s    = idx >> 5;
    float invf = (float)pow(10000.0, -(double)lane / 32.0);
    float sn, cs;
    sincosf((float)s * invf, &sn, &cs);
    g_costab[idx] = cs;
    g_sintab[idx] = sn;
}

// ---------------------------------------------------------------------------
// X split: f32 -> fp16 hi/lo into g_A2 (row 2048: [hi(1024) | lo(1024)])
// ---------------------------------------------------------------------------
__global__ void split_x(const float* __restrict__ in)
{
    int i = blockIdx.x * blockDim.x + threadIdx.x;   // float4 index
    if (i >= MROWS * 256) return;
    int r = i >> 8, c4 = i & 255;
    float4 v = ((const float4*)in)[i];
    __half2 h01 = __floats2half2_rn(v.x, v.y);
    __half2 h23 = __floats2half2_rn(v.z, v.w);
    __half2 l01 = __floats2half2_rn(v.x - __half2float(__low2half(h01)),
                                    v.y - __half2float(__high2half(h01)));
    __half2 l23 = __floats2half2_rn(v.z - __half2float(__low2half(h23)),
                                    v.w - __half2float(__high2half(h23)));
    size_t base = (size_t)r * 2048 + c4 * 4;
    h4 hv; hv.a = h01; hv.b = h23;
    h4 lv; lv.a = l01; lv.b = l23;
    *(h4*)(g_A2 + base)        = hv;
    *(h4*)(g_A2 + base + 1024) = lv;
}

// ---------------------------------------------------------------------------
// W convert: f32 -> fp16 (row 1024). which: 0 -> g_B2, 1 -> g_B2o
// ---------------------------------------------------------------------------
__global__ void split_w(const float* __restrict__ in, int which)
{
    int i = blockIdx.x * blockDim.x + threadIdx.x;   // float4 index
    if (i >= DIM * 256) return;
    float4 v = ((const float4*)in)[i];
    h4 hv;
    hv.a = __floats2half2_rn(v.x, v.y);
    hv.b = __floats2half2_rn(v.z, v.w);
    __half* out = which ? g_B2o : g_B2;
    *(h4*)(out + (size_t)i * 4) = hv;
}

// ---------------------------------------------------------------------------
// mma.sync fp16x2 GEMM (unchanged, 129us measured)
// ---------------------------------------------------------------------------
#define NST      32
#define STAGE_B  (128*144)
#define GEMM_SMEM (4*STAGE_B)            // 73728

__global__ __launch_bounds__(256)
void gemm_mma(const float* __restrict__ bias, float* __restrict__ dst_param,
              int mode, int bsel)
{
    extern __shared__ __align__(16) char sm[];
    uint32_t sb = smem_u32(sm);

    const __half* Bmat = bsel ? g_B2o : g_B2;

    int tid  = threadIdx.x;
    int lane = tid & 31;
    int wid  = tid >> 5;
    int wm   = wid & 1;
    int wn   = wid >> 1;
    int m0 = blockIdx.y << 7, n0 = blockIdx.x << 7;

    int lr = ((lane >> 3) & 1) * 8 + (lane & 7);
    int lk = (lane >> 4) * 8;

    float c[4][4][4];
    #pragma unroll
    for (int mf = 0; mf < 4; mf++)
        #pragma unroll
        for (int nf = 0; nf < 4; nf++)
            #pragma unroll
            for (int v = 0; v < 4; v++) c[mf][nf][v] = 0.0f;

    auto load_stage = [&](int t, int buf) {
        int kp = t << 6;
        int bc = kp & 1023;
        const __half* Ab = g_A2 + (size_t)m0 * 2048 + kp;
        const __half* Bb = Bmat + (size_t)n0 * 1024 + bc;
        uint32_t sa  = sb + buf * STAGE_B;
        uint32_t sbb = sb + 2 * STAGE_B + buf * STAGE_B;
        #pragma unroll
        for (int it = 0; it < 4; it++) {
            int id = tid + (it << 8);
            int r = id >> 3, ch = id & 7;
            CP_ASYNC16(sa  + r * 144 + (ch << 4), Ab + (size_t)r * 2048 + (ch << 3));
            CP_ASYNC16(sbb + r * 144 + (ch << 4), Bb + (size_t)r * 1024 + (ch << 3));
        }
        CP_COMMIT();
    };

    load_stage(0, 0);

    #pragma unroll 1
    for (int t = 0; t < NST; t++) {
        CP_WAIT0();
        __syncthreads();
        if (t + 1 < NST) load_stage(t + 1, (t + 1) & 1);

        uint32_t sa  = sb + (t & 1) * STAGE_B;
        uint32_t sbb = sb + 2 * STAGE_B + (t & 1) * STAGE_B;

        #pragma unroll
        for (int kk = 0; kk < 64; kk += 16) {
            uint32_t a[4][4];
            #pragma unroll
            for (int mf = 0; mf < 4; mf++) {
                uint32_t ad = sa + (uint32_t)(wm * 64 + mf * 16 + lr) * 144 + (kk + lk) * 2;
                LDMATRIX_X4(a[mf][0], a[mf][1], a[mf][2], a[mf][3], ad);
            }
            uint32_t b[2][4];
            #pragma unroll
            for (int nb = 0; nb < 2; nb++) {
                uint32_t bd = sbb + (uint32_t)(wn * 32 + nb * 16 + lr) * 144 + (kk + lk) * 2;
                LDMATRIX_X4(b[nb][0], b[nb][1], b[nb][2], b[nb][3], bd);
            }
            #pragma unroll
            for (int mf = 0; mf < 4; mf++) {
                #pragma unroll
                for (int nf = 0; nf < 4; nf++) {
                    int nb = nf >> 1;
                    uint32_t b0 = (nf & 1) ? b[nb][1] : b[nb][0];
                    uint32_t b1 = (nf & 1) ? b[nb][3] : b[nb][2];
                    MMA_F16(c[mf][nf], a[mf], b0, b1);
                }
            }
        }
        __syncthreads();
    }

    int rq = lane >> 2, cq = (lane & 3) * 2;
    float2 bv[4];
    #pragma unroll
    for (int nf = 0; nf < 4; nf++) {
        int col = n0 + wn * 32 + nf * 8 + cq;
        bv[nf] = make_float2(bias[col], bias[col + 1]);
    }

    #pragma unroll
    for (int mf = 0; mf < 4; mf++) {
        #pragma unroll
        for (int nf = 0; nf < 4; nf++) {
            int r   = m0 + wm * 64 + mf * 16 + rq;
            int col = n0 + wn * 32 + nf * 8 + cq;
            float2 lo = make_float2(c[mf][nf][0] + bv[nf].x, c[mf][nf][1] + bv[nf].y);
            float2 hi = make_float2(c[mf][nf][2] + bv[nf].x, c[mf][nf][3] + bv[nf].y);
            if (mode == 3) {
                *(float2*)(dst_param + (size_t)r * 1024 + col)       = lo;
                *(float2*)(dst_param + (size_t)(r + 8) * 1024 + col) = hi;
            } else {
                float* g = (mode == 0) ? g_Q : (mode == 1) ? g_K : g_V;
                int h = col >> 6, d0 = col & 63;
                int b1 = r >> 11, s1 = r & 2047;
                *(float2*)(g + (((size_t)(b1 * NH + h) * SEQ + s1) << 6) + d0) = lo;
                int s2 = (r + 8) & 2047;
                *(float2*)(g + (((size_t)(b1 * NH + h) * SEQ + s2) << 6) + d0) = hi;
            }
        }
    }
}

// ---------------------------------------------------------------------------
// Fused RoPE + fp16 hi/lo conversion — now table-driven (NO pow/sincos).
// blockIdx.y: 0=Q (rope+scale), 1=K (rope), 2=V (plain).
// ---------------------------------------------------------------------------
#define QSCALE 0.18033688011112042f   // 0.125 * log2(e)

__global__ void conv_rope()
{
    int gw   = (blockIdx.x * blockDim.x + threadIdx.x) >> 5;
    int lane = threadIdx.x & 31;
    int which = blockIdx.y;
    const float* src = (which == 0) ? g_Q : (which == 1) ? g_K : g_V;
    __half* dh = (which == 0) ? g_Qh : (which == 1) ? g_Kh : g_Vh;
    __half* dl = (which == 0) ? g_Ql : (which == 1) ? g_Kl : g_Vl;
    int s = gw & (SEQ - 1);
    const float* row = src + (size_t)gw * HD;

    float v0, v1;
    if (which < 2) {
        int ti = (s << 5) + lane;
        float cs = g_costab[ti];
        float sn = g_sintab[ti];
        float xe   = row[lane];
        float xe32 = row[lane + 32];
        float x2e  = row[2 * lane];
        float x2e1 = row[2 * lane + 1];
        v0 = xe   * cs - x2e1 * sn;
        v1 = xe32 * cs + x2e  * sn;
        if (which == 0) { v0 *= QSCALE; v1 *= QSCALE; }
    } else {
        v0 = row[lane];
        v1 = row[lane + 32];
    }
    __half h0 = __float2half_rn(v0);
    __half h1 = __float2half_rn(v1);
    size_t o = (size_t)gw * HD;
    dh[o + lane]      = h0;
    dh[o + lane + 32] = h1;
    dl[o + lane]      = __float2half_rn(v0 - __half2float(h0));
    dl[o + lane + 32] = __float2half_rn(v1 - __half2float(h1));
}

// ---------------------------------------------------------------------------
// Flash attention (R11 version, unchanged): BM=128 (8 warps), BN=64,
// Q persistent in SMEM, launch_bounds(256,2), f32 ex2 softmax, ones-MMA sums.
// SMEM: Qhi 18432 | Qlo 18432 | KV stage0 36864 | KV stage1 36864 = 110592.
// ---------------------------------------------------------------------------
#define ROWB 144
#define QSM  18432
#define PLANE (64*ROWB)
#define KVST (4*PLANE)
#define ATTN_SMEM (2*QSM + 2*KVST)   // 110592

__global__ __launch_bounds__(256, 2)
void attn_mma()
{
    extern __shared__ __align__(16) char smb[];
    uint32_t sb = smem_u32(smb);

    int tid  = threadIdx.x;
    int lane = tid & 31;
    int wid  = tid >> 5;                    // 0..7
    int bh   = blockIdx.y;
    int bx   = gridDim.x - 1 - blockIdx.x;  // heaviest CTAs first
    int q0   = bx << 7;
    int nt   = 2 * bx + 2;

    const __half* Kh = g_Kh + (size_t)bh * SEQ * HD;
    const __half* Kl = g_Kl + (size_t)bh * SEQ * HD;
    const __half* Vh = g_Vh + (size_t)bh * SEQ * HD;
    const __half* Vl = g_Vl + (size_t)bh * SEQ * HD;

    int lr = ((lane >> 3) & 1) * 8 + (lane & 7);
    int lk = (lane >> 4) * 8;
    int rq = lane >> 2, cq = (lane & 3) * 2;

    auto load_kv = [&](int t, int stage) {
        int k0 = t << 6;
        uint32_t base = sb + 2*QSM + stage * KVST;
        #pragma unroll
        for (int it = 0; it < 2; it++) {
            int id = tid + (it << 8);
            int r = id >> 3, ch = id & 7;
            uint32_t o = r * ROWB + (ch << 4);
            int go = ((k0 + r) << 6) + (ch << 3);
            CP_ASYNC16(base + o,             Kh + go);
            CP_ASYNC16(base + PLANE + o,     Kl + go);
            CP_ASYNC16(base + 2*PLANE + o,   Vh + go);
            CP_ASYNC16(base + 3*PLANE + o,   Vl + go);
        }
        CP_COMMIT();
    };

    // prologue: Q hi/lo into persistent planes
    {
        const __half* Qh = g_Qh + (size_t)bh * SEQ * HD;
        const __half* Ql = g_Ql + (size_t)bh * SEQ * HD;
        #pragma unroll
        for (int it = 0; it < 8; it++) {
            int id = tid + (it << 8);          // 0..2047
            int pl = id >> 10;                 // 0=hi, 1=lo
            int rem = id & 1023;
            int r = rem >> 3, ch = rem & 7;
            uint32_t o = pl * QSM + r * ROWB + (ch << 4);
            const __half* src = pl ? Ql : Qh;
            CP_ASYNC16(sb + o, src + ((q0 + r) << 6) + (ch << 3));
        }
        CP_COMMIT();
    }
    load_kv(0, 0);

    float acc[8][4];
    #pragma unroll
    for (int nf = 0; nf < 8; nf++)
        #pragma unroll
        for (int v = 0; v < 4; v++) acc[nf][v] = 0.0f;
    float lacc[4] = {0.0f, 0.0f, 0.0f, 0.0f};
    float m_i[2] = {-1e30f, -1e30f};

    int wminrow = q0 + wid*16;

    CP_WAIT0();
    __syncthreads();

    #pragma unroll 1
    for (int t = 0; t < nt; t++) {
        int k0 = t << 6;
        if (t + 1 < nt) { load_kv(t + 1, (t + 1) & 1); CP_WAIT1(); }
        __syncthreads();

        uint32_t khb = sb + 2*QSM + (t & 1) * KVST;
        uint32_t klb = khb + PLANE;
        uint32_t vhb = khb + 2*PLANE;
        uint32_t vlb = khb + 3*PLANE;

        // ---- S = Q K^T (3-term hi/lo), Q fragments reloaded per kc ----
        float sc[8][4];
        #pragma unroll
        for (int nf = 0; nf < 8; nf++)
            #pragma unroll
            for (int v = 0; v < 4; v++) sc[nf][v] = 0.0f;

        #pragma unroll
        for (int kc = 0; kc < 4; kc++) {
            uint32_t qoff = (uint32_t)(wid*16 + lr) * ROWB + (kc*16 + lk) * 2;
            uint32_t qh[4], ql[4];
            LDMATRIX_X4(qh[0], qh[1], qh[2], qh[3], sb + qoff);
            LDMATRIX_X4(ql[0], ql[1], ql[2], ql[3], sb + QSM + qoff);
            #pragma unroll
            for (int nb = 0; nb < 4; nb++) {
                uint32_t off = (uint32_t)(nb*16 + lr) * ROWB + (kc*16 + lk) * 2;
                uint32_t bh0, bh1, bh2, bh3, bl0, bl1, bl2, bl3;
                LDMATRIX_X4(bh0, bh1, bh2, bh3, khb + off);
                LDMATRIX_X4(bl0, bl1, bl2, bl3, klb + off);
                MMA_F16(sc[2*nb],   qh, bh0, bh2);
                MMA_F16(sc[2*nb],   ql, bh0, bh2);
                MMA_F16(sc[2*nb],   qh, bl0, bl2);
                MMA_F16(sc[2*nb+1], qh, bh1, bh3);
                MMA_F16(sc[2*nb+1], ql, bh1, bh3);
                MMA_F16(sc[2*nb+1], qh, bl1, bl3);
            }
        }

        // ---- causal mask ----
        if (k0 + 63 > wminrow) {
            int row0 = wminrow + rq;
            #pragma unroll
            for (int nf = 0; nf < 8; nf++) {
                int col = k0 + nf*8 + cq;
                if (col     > row0)     sc[nf][0] = -1e30f;
                if (col + 1 > row0)     sc[nf][1] = -1e30f;
                if (col     > row0 + 8) sc[nf][2] = -1e30f;
                if (col + 1 > row0 + 8) sc[nf][3] = -1e30f;
            }
        }

        // ---- online softmax: f32 ex2, pack to f16x2 ----
        uint32_t pr[8][2];
        #pragma unroll
        for (int i = 0; i < 2; i++) {
            float mx = -1e30f;
            #pragma unroll
            for (int nf = 0; nf < 8; nf++)
                mx = fmaxf(mx, fmaxf(sc[nf][2*i], sc[nf][2*i+1]));
            mx = fmaxf(mx, __shfl_xor_sync(0xffffffffu, mx, 1));
            mx = fmaxf(mx, __shfl_xor_sync(0xffffffffu, mx, 2));
            float mnew  = fmaxf(m_i[i], mx);
            float scale = ex2f(m_i[i] - mnew);
            float neg   = -mnew;
            #pragma unroll
            for (int nf = 0; nf < 8; nf++) {
                float p0 = ex2f(sc[nf][2*i]   + neg);
                float p1 = ex2f(sc[nf][2*i+1] + neg);
                asm("cvt.rn.f16x2.f32 %0, %1, %2;" : "=r"(pr[nf][i]) : "f"(p1), "f"(p0));
            }
            m_i[i] = mnew;
            lacc[2*i]   *= scale;
            lacc[2*i+1] *= scale;
            #pragma unroll
            for (int nf = 0; nf < 8; nf++) {
                acc[nf][2*i]   *= scale;
                acc[nf][2*i+1] *= scale;
            }
        }

        // ---- ctx += P * (Vhi + Vlo); row sums via ones-MMA ----
        #pragma unroll
        for (int kc = 0; kc < 4; kc++) {
            uint32_t ph[4] = { pr[2*kc][0], pr[2*kc][1], pr[2*kc+1][0], pr[2*kc+1][1] };
            MMA_F16(lacc, ph, 0x3C003C00u, 0x3C003C00u);
            #pragma unroll
            for (int db = 0; db < 4; db++) {
                uint32_t off = (uint32_t)(kc*16 + (lane & 15)) * ROWB
                             + (db*16 + ((lane >> 4) << 3)) * 2;
                uint32_t vh0, vh1, vh2, vh3, vl0, vl1, vl2, vl3;
                LDMATRIX_X4T(vh0, vh1, vh2, vh3, vhb + off);
                LDMATRIX_X4T(vl0, vl1, vl2, vl3, vlb + off);
                MMA_F16(acc[2*db],   ph, vh0, vh1);
                MMA_F16(acc[2*db],   ph, vl0, vl1);
                MMA_F16(acc[2*db+1], ph, vh2, vh3);
                MMA_F16(acc[2*db+1], ph, vl2, vl3);
            }
        }
        __syncthreads();
    }

    // ---- epilogue: normalize + fp16 hi/lo split straight into g_A2 ----
    int b = bh >> 4, h = bh & 15;
    #pragma unroll
    for (int i = 0; i < 2; i++) {
        float inv = 1.0f / lacc[2*i];
        int s = q0 + wid*16 + rq + 8*i;
        __half* rowp = g_A2 + ((size_t)(b * SEQ + s) << 11) + (h << 6);
        #pragma unroll
        for (int nf = 0; nf < 8; nf++) {
            float v0 = acc[nf][2*i]   * inv;
            float v1 = acc[nf][2*i+1] * inv;
            __half2 hv = __floats2half2_rn(v0, v1);
            __half2 lv = __floats2half2_rn(v0 - __half2float(__low2half(hv)),
                                           v1 - __half2float(__high2half(hv)));
            *(__half2*)(rowp + nf*8 + cq)        = hv;
            *(__half2*)(rowp + 1024 + nf*8 + cq) = lv;
        }
    }
}

// ---------------------------------------------------------------------------
extern "C" void kernel_launch(void* const* d_in, const int* in_sizes, int n_in,
                              void* d_out, int out_size)
{
    const float* query = (const float*)d_in[0];
    const float* key   = (const float*)d_in[1];
    const float* value = (const float*)d_in[2];
    const float* w_q = (const float*)d_in[4];
    const float* b_q = (const float*)d_in[5];
    const float* w_k = (const float*)d_in[6];
    const float* b_k = (const float*)d_in[7];
    const float* w_v = (const float*)d_in[8];
    const float* b_v = (const float*)d_in[9];
    const float* w_o = (const float*)d_in[10];
    const float* b_o = (const float*)d_in[11];
    float* out = (float*)d_out;

    static int attr_set = 0;
    if (!attr_set) {
        cudaFuncSetAttribute(gemm_mma, cudaFuncAttributeMaxDynamicSharedMemorySize, GEMM_SMEM);
        cudaFuncSetAttribute(attn_mma, cudaFuncAttributeMaxDynamicSharedMemorySize, ATTN_SMEM);
        attr_set = 1;
    }

    dim3 ggrid(DIM / 128, MROWS / 128);   // (8, 64)

    init_tbl<<<SEQ*32/256, 256>>>();                // 0
    split_x<<<MROWS, 256>>>(query);                 // 1
    split_w<<<DIM,   256>>>(w_q, 0);                // 2
    gemm_mma<<<ggrid, 256, GEMM_SMEM>>>(b_q, nullptr, 0, 0);  // 3 <- profiled

    split_w<<<DIM,   256>>>(w_o, 1);                // 4
    split_x<<<MROWS, 256>>>(key);                   // 5
    split_w<<<DIM,   256>>>(w_k, 0);                // 6
    gemm_mma<<<ggrid, 256, GEMM_SMEM>>>(b_k, nullptr, 1, 0);  // 7

    split_x<<<MROWS, 256>>>(value);                 // 8
    split_w<<<DIM,   256>>>(w_v, 0);                // 9
    gemm_mma<<<ggrid, 256, GEMM_SMEM>>>(b_v, nullptr, 2, 0);  // 10

    conv_rope<<<dim3(BATCH*NH*SEQ/8, 3), 256>>>();  // 11
    attn_mma<<<dim3(SEQ/128, BATCH*NH), 256, ATTN_SMEM>>>();  // 12

    gemm_mma<<<ggrid, 256, GEMM_SMEM>>>(b_o, out, 3, 1);      // 13
}

// round 13
// speedup vs baseline: 2.4022x; 1.0408x over previous
#include <cuda_runtime.h>
#include <cuda_fp16.h>
#include <math.h>
#include <stdint.h>

#define BATCH 4
#define SEQ   2048
#define DIM   1024
#define NH    16
#define HD    64
#define MROWS (BATCH*SEQ)
#define ASZ   ((size_t)MROWS*2048)

// ---------------------------------------------------------------------------
// Scratch (__device__ globals; allocation-free rule)
// ---------------------------------------------------------------------------
__device__ float g_Q[BATCH*NH*SEQ*HD];
__device__ float g_K[BATCH*NH*SEQ*HD];
__device__ float g_V[BATCH*NH*SEQ*HD];
// fp16x2 GEMM A operands: 3 buffers of [Xhi | Xlo] rows (width 2048).
// Buffer 0 doubles as the attention-context buffer for the o-projection.
__device__ __half g_A3[3*ASZ];
// fp16 weights: g_B2 = concat [Wq; Wk; Wv] (3 x 1024x1024), g_B2o = Wo
__device__ __half g_B2[(size_t)3*DIM*DIM];
__device__ __half g_B2o[(size_t)DIM*DIM];
// fp16 hi/lo planes for attention (RoPE + scale pre-applied to Q/K)
__device__ __half g_Qh[BATCH*NH*SEQ*HD];
__device__ __half g_Ql[BATCH*NH*SEQ*HD];
__device__ __half g_Kh[BATCH*NH*SEQ*HD];
__device__ __half g_Kl[BATCH*NH*SEQ*HD];
__device__ __half g_Vh[BATCH*NH*SEQ*HD];
__device__ __half g_Vl[BATCH*NH*SEQ*HD];
// RoPE tables
__device__ float g_costab[SEQ*32];
__device__ float g_sintab[SEQ*32];

__device__ __forceinline__ uint32_t smem_u32(const void* p) {
    uint32_t a;
    asm("{ .reg .u64 t; cvta.to.shared.u64 t, %1; cvt.u32.u64 %0, t; }" : "=r"(a) : "l"(p));
    return a;
}

#define LDMATRIX_X4(r0, r1, r2, r3, addr) \
    asm volatile("ldmatrix.sync.aligned.m8n8.x4.shared.b16 {%0,%1,%2,%3}, [%4];" \
        : "=r"(r0), "=r"(r1), "=r"(r2), "=r"(r3) : "r"(addr))

#define LDMATRIX_X4T(r0, r1, r2, r3, addr) \
    asm volatile("ldmatrix.sync.aligned.m8n8.x4.trans.shared.b16 {%0,%1,%2,%3}, [%4];" \
        : "=r"(r0), "=r"(r1), "=r"(r2), "=r"(r3) : "r"(addr))

#define MMA_F16(c, a, b0v, b1v) \
    asm volatile("mma.sync.aligned.m16n8k16.row.col.f32.f16.f16.f32 " \
        "{%0,%1,%2,%3}, {%4,%5,%6,%7}, {%8,%9}, {%0,%1,%2,%3};" \
        : "+f"((c)[0]), "+f"((c)[1]), "+f"((c)[2]), "+f"((c)[3]) \
        : "r"((a)[0]), "r"((a)[1]), "r"((a)[2]), "r"((a)[3]), "r"(b0v), "r"(b1v))

#define CP_ASYNC16(dst, src) \
    asm volatile("cp.async.cg.shared.global [%0], [%1], 16;" :: "r"(dst), "l"(src))
#define CP_COMMIT() asm volatile("cp.async.commit_group;" ::: "memory")
#define CP_WAIT0()  asm volatile("cp.async.wait_group 0;" ::: "memory")
#define CP_WAIT1()  asm volatile("cp.async.wait_group 1;" ::: "memory")

__device__ __forceinline__ uint32_t h2u(__half2 h) { return *reinterpret_cast<uint32_t*>(&h); }
__device__ __forceinline__ float ex2f(float x) {
    float y; asm("ex2.approx.f32 %0, %1;" : "=f"(y) : "f"(x)); return y;
}

struct h4 { __half2 a, b; };

// ---------------------------------------------------------------------------
// RoPE table init (65536 pow/sincos total, bit-identical to reference math)
// ---------------------------------------------------------------------------
__global__ void init_tbl()
{
    int idx = blockIdx.x * blockDim.x + threadIdx.x;
    if (idx >= SEQ * 32) return;
    int lane = idx & 31;
    int s    = idx >> 5;
    float invf = (float)pow(10000.0, -(double)lane / 32.0);
    float sn, cs;
    sincosf((float)s * invf, &sn, &cs);
    g_costab[idx] = cs;
    g_sintab[idx] = sn;
}

// ---------------------------------------------------------------------------
// X split x3: f32 -> fp16 hi/lo into g_A3[z]  (z = blockIdx.z: 0=q,1=k,2=v)
// ---------------------------------------------------------------------------
__global__ void split_x3(const float* __restrict__ q, const float* __restrict__ k,
                         const float* __restrict__ v)
{
    int z = blockIdx.z;
    const float* src = (z == 0) ? q : (z == 1) ? k : v;
    int i = blockIdx.x * blockDim.x + threadIdx.x;
    if (i >= MROWS * 256) return;
    int r = i >> 8, c4 = i & 255;
    float4 vv = ((const float4*)src)[i];
    __half2 h01 = __floats2half2_rn(vv.x, vv.y);
    __half2 h23 = __floats2half2_rn(vv.z, vv.w);
    __half2 l01 = __floats2half2_rn(vv.x - __half2float(__low2half(h01)),
                                    vv.y - __half2float(__high2half(h01)));
    __half2 l23 = __floats2half2_rn(vv.z - __half2float(__low2half(h23)),
                                    vv.w - __half2float(__high2half(h23)));
    __half* out = g_A3 + (size_t)z * ASZ;
    size_t base = (size_t)r * 2048 + c4 * 4;
    h4 hv; hv.a = h01; hv.b = h23;
    h4 lv; lv.a = l01; lv.b = l23;
    *(h4*)(out + base)        = hv;
    *(h4*)(out + base + 1024) = lv;
}

// ---------------------------------------------------------------------------
// W convert x3: f32 -> fp16 concat into g_B2 (z picks wq/wk/wv)
// ---------------------------------------------------------------------------
__global__ void split_w3(const float* __restrict__ wq, const float* __restrict__ wk,
                         const float* __restrict__ wv)
{
    int z = blockIdx.z;
    const float* src = (z == 0) ? wq : (z == 1) ? wk : wv;
    int i = blockIdx.x * blockDim.x + threadIdx.x;
    if (i >= DIM * 256) return;
    float4 v = ((const float4*)src)[i];
    h4 hv;
    hv.a = __floats2half2_rn(v.x, v.y);
    hv.b = __floats2half2_rn(v.z, v.w);
    *(h4*)(g_B2 + (size_t)z * DIM * DIM + (size_t)i * 4) = hv;
}

__global__ void split_wo(const float* __restrict__ in)
{
    int i = blockIdx.x * blockDim.x + threadIdx.x;
    if (i >= DIM * 256) return;
    float4 v = ((const float4*)in)[i];
    h4 hv;
    hv.a = __floats2half2_rn(v.x, v.y);
    hv.b = __floats2half2_rn(v.z, v.w);
    *(h4*)(g_B2o + (size_t)i * 4) = hv;
}

// ---------------------------------------------------------------------------
// mma.sync fp16x2 GEMM, 3-stage cp.async pipeline, fused-QKV capable.
// opro=0: gridDim.z=3, z selects A buffer / weight block / bias / QKV dst.
// opro=1: single z, A=g_A3[0] (attention ctx), B=g_B2o, row-major dst.
// ---------------------------------------------------------------------------
#define NST      32
#define STAGE_B  (128*144)
#define GEMM_SMEM (6*STAGE_B)            // 110592 (3 stages x A,B)

__global__ __launch_bounds__(256)
void gemm_mma(const float* __restrict__ b0, const float* __restrict__ b1,
              const float* __restrict__ b2, float* __restrict__ dst_param,
              int opro)
{
    extern __shared__ __align__(16) char sm[];
    uint32_t sb = smem_u32(sm);

    int z = blockIdx.z;
    int mode = opro ? 3 : z;
    const float* bias = opro ? b0 : (z == 0) ? b0 : (z == 1) ? b1 : b2;
    const __half* Amat = g_A3 + (opro ? 0 : (size_t)z * ASZ);
    const __half* Bmat = opro ? g_B2o : g_B2 + (size_t)z * DIM * DIM;

    int tid  = threadIdx.x;
    int lane = tid & 31;
    int wid  = tid >> 5;
    int wm   = wid & 1;
    int wn   = wid >> 1;
    int m0 = blockIdx.y << 7, n0 = blockIdx.x << 7;

    int lr = ((lane >> 3) & 1) * 8 + (lane & 7);
    int lk = (lane >> 4) * 8;

    float c[4][4][4];
    #pragma unroll
    for (int mf = 0; mf < 4; mf++)
        #pragma unroll
        for (int nf = 0; nf < 4; nf++)
            #pragma unroll
            for (int v = 0; v < 4; v++) c[mf][nf][v] = 0.0f;

    auto load_stage = [&](int t, int buf) {
        int kp = t << 6;
        int bc = kp & 1023;
        const __half* Ab = Amat + (size_t)m0 * 2048 + kp;
        const __half* Bb = Bmat + (size_t)n0 * 1024 + bc;
        uint32_t sa  = sb + buf * STAGE_B;
        uint32_t sbb = sb + 3 * STAGE_B + buf * STAGE_B;
        #pragma unroll
        for (int it = 0; it < 4; it++) {
            int id = tid + (it << 8);
            int r = id >> 3, ch = id & 7;
            CP_ASYNC16(sa  + r * 144 + (ch << 4), Ab + (size_t)r * 2048 + (ch << 3));
            CP_ASYNC16(sbb + r * 144 + (ch << 4), Bb + (size_t)r * 1024 + (ch << 3));
        }
        CP_COMMIT();
    };

    load_stage(0, 0);
    load_stage(1, 1);

    #pragma unroll 1
    for (int t = 0; t < NST; t++) {
        if (t + 1 < NST) { CP_WAIT1(); } else { CP_WAIT0(); }
        __syncthreads();
        if (t + 2 < NST) load_stage(t + 2, (t + 2) % 3);

        int buf = t % 3;
        uint32_t sa  = sb + buf * STAGE_B;
        uint32_t sbb = sb + 3 * STAGE_B + buf * STAGE_B;

        #pragma unroll
        for (int kk = 0; kk < 64; kk += 16) {
            uint32_t a[4][4];
            #pragma unroll
            for (int mf = 0; mf < 4; mf++) {
                uint32_t ad = sa + (uint32_t)(wm * 64 + mf * 16 + lr) * 144 + (kk + lk) * 2;
                LDMATRIX_X4(a[mf][0], a[mf][1], a[mf][2], a[mf][3], ad);
            }
            uint32_t b[2][4];
            #pragma unroll
            for (int nb = 0; nb < 2; nb++) {
                uint32_t bd = sbb + (uint32_t)(wn * 32 + nb * 16 + lr) * 144 + (kk + lk) * 2;
                LDMATRIX_X4(b[nb][0], b[nb][1], b[nb][2], b[nb][3], bd);
            }
            #pragma unroll
            for (int mf = 0; mf < 4; mf++) {
                #pragma unroll
                for (int nf = 0; nf < 4; nf++) {
                    int nb = nf >> 1;
                    uint32_t bb0 = (nf & 1) ? b[nb][1] : b[nb][0];
                    uint32_t bb1 = (nf & 1) ? b[nb][3] : b[nb][2];
                    MMA_F16(c[mf][nf], a[mf], bb0, bb1);
                }
            }
        }
        __syncthreads();
    }

    int rq = lane >> 2, cq = (lane & 3) * 2;
    float2 bv[4];
    #pragma unroll
    for (int nf = 0; nf < 4; nf++) {
        int col = n0 + wn * 32 + nf * 8 + cq;
        bv[nf] = make_float2(bias[col], bias[col + 1]);
    }

    #pragma unroll
    for (int mf = 0; mf < 4; mf++) {
        #pragma unroll
        for (int nf = 0; nf < 4; nf++) {
            int r   = m0 + wm * 64 + mf * 16 + rq;
            int col = n0 + wn * 32 + nf * 8 + cq;
            float2 lo = make_float2(c[mf][nf][0] + bv[nf].x, c[mf][nf][1] + bv[nf].y);
            float2 hi = make_float2(c[mf][nf][2] + bv[nf].x, c[mf][nf][3] + bv[nf].y);
            if (mode == 3) {
                *(float2*)(dst_param + (size_t)r * 1024 + col)       = lo;
                *(float2*)(dst_param + (size_t)(r + 8) * 1024 + col) = hi;
            } else {
                float* g = (mode == 0) ? g_Q : (mode == 1) ? g_K : g_V;
                int h = col >> 6, d0 = col & 63;
                int b1i = r >> 11, s1 = r & 2047;
                *(float2*)(g + (((size_t)(b1i * NH + h) * SEQ + s1) << 6) + d0) = lo;
                int s2 = (r + 8) & 2047;
                *(float2*)(g + (((size_t)(b1i * NH + h) * SEQ + s2) << 6) + d0) = hi;
            }
        }
    }
}

// ---------------------------------------------------------------------------
// Fused RoPE + fp16 hi/lo conversion — table-driven.
// ---------------------------------------------------------------------------
#define QSCALE 0.18033688011112042f   // 0.125 * log2(e)

__global__ void conv_rope()
{
    int gw   = (blockIdx.x * blockDim.x + threadIdx.x) >> 5;
    int lane = threadIdx.x & 31;
    int which = blockIdx.y;
    const float* src = (which == 0) ? g_Q : (which == 1) ? g_K : g_V;
    __half* dh = (which == 0) ? g_Qh : (which == 1) ? g_Kh : g_Vh;
    __half* dl = (which == 0) ? g_Ql : (which == 1) ? g_Kl : g_Vl;
    int s = gw & (SEQ - 1);
    const float* row = src + (size_t)gw * HD;

    float v0, v1;
    if (which < 2) {
        int ti = (s << 5) + lane;
        float cs = g_costab[ti];
        float sn = g_sintab[ti];
        float xe   = row[lane];
        float xe32 = row[lane + 32];
        float x2e  = row[2 * lane];
        float x2e1 = row[2 * lane + 1];
        v0 = xe   * cs - x2e1 * sn;
        v1 = xe32 * cs + x2e  * sn;
        if (which == 0) { v0 *= QSCALE; v1 *= QSCALE; }
    } else {
        v0 = row[lane];
        v1 = row[lane + 32];
    }
    __half h0 = __float2half_rn(v0);
    __half h1 = __float2half_rn(v1);
    size_t o = (size_t)gw * HD;
    dh[o + lane]      = h0;
    dh[o + lane + 32] = h1;
    dl[o + lane]      = __float2half_rn(v0 - __half2float(h0));
    dl[o + lane + 32] = __float2half_rn(v1 - __half2float(h1));
}

// ---------------------------------------------------------------------------
// Flash attention (R11/R12 version): BM=128 (8 warps), BN=64, Q in SMEM,
// launch_bounds(256,2), f32 ex2 softmax, ones-MMA sums.
// Epilogue writes fp16 hi/lo ctx into g_A3[0] for the o-projection.
// ---------------------------------------------------------------------------
#define ROWB 144
#define QSM  18432
#define PLANE (64*ROWB)
#define KVST (4*PLANE)
#define ATTN_SMEM (2*QSM + 2*KVST)   // 110592

__global__ __launch_bounds__(256, 2)
void attn_mma()
{
    extern __shared__ __align__(16) char smb[];
    uint32_t sb = smem_u32(smb);

    int tid  = threadIdx.x;
    int lane = tid & 31;
    int wid  = tid >> 5;
    int bh   = blockIdx.y;
    int bx   = gridDim.x - 1 - blockIdx.x;
    int q0   = bx << 7;
    int nt   = 2 * bx + 2;

    const __half* Kh = g_Kh + (size_t)bh * SEQ * HD;
    const __half* Kl = g_Kl + (size_t)bh * SEQ * HD;
    const __half* Vh = g_Vh + (size_t)bh * SEQ * HD;
    const __half* Vl = g_Vl + (size_t)bh * SEQ * HD;

    int lr = ((lane >> 3) & 1) * 8 + (lane & 7);
    int lk = (lane >> 4) * 8;
    int rq = lane >> 2, cq = (lane & 3) * 2;

    auto load_kv = [&](int t, int stage) {
        int k0 = t << 6;
        uint32_t base = sb + 2*QSM + stage * KVST;
        #pragma unroll
        for (int it = 0; it < 2; it++) {
            int id = tid + (it << 8);
            int r = id >> 3, ch = id & 7;
            uint32_t o = r * ROWB + (ch << 4);
            int go = ((k0 + r) << 6) + (ch << 3);
            CP_ASYNC16(base + o,             Kh + go);
            CP_ASYNC16(base + PLANE + o,     Kl + go);
            CP_ASYNC16(base + 2*PLANE + o,   Vh + go);
            CP_ASYNC16(base + 3*PLANE + o,   Vl + go);
        }
        CP_COMMIT();
    };

    // prologue: Q hi/lo into persistent planes
    {
        const __half* Qh = g_Qh + (size_t)bh * SEQ * HD;
        const __half* Ql = g_Ql + (size_t)bh * SEQ * HD;
        #pragma unroll
        for (int it = 0; it < 8; it++) {
            int id = tid + (it << 8);
            int pl = id >> 10;
            int rem = id & 1023;
            int r = rem >> 3, ch = rem & 7;
            uint32_t o = pl * QSM + r * ROWB + (ch << 4);
            const __half* src = pl ? Ql : Qh;
            CP_ASYNC16(sb + o, src + ((q0 + r) << 6) + (ch << 3));
        }
        CP_COMMIT();
    }
    load_kv(0, 0);

    float acc[8][4];
    #pragma unroll
    for (int nf = 0; nf < 8; nf++)
        #pragma unroll
        for (int v = 0; v < 4; v++) acc[nf][v] = 0.0f;
    float lacc[4] = {0.0f, 0.0f, 0.0f, 0.0f};
    float m_i[2] = {-1e30f, -1e30f};

    int wminrow = q0 + wid*16;

    CP_WAIT0();
    __syncthreads();

    #pragma unroll 1
    for (int t = 0; t < nt; t++) {
        int k0 = t << 6;
        if (t + 1 < nt) { load_kv(t + 1, (t + 1) & 1); CP_WAIT1(); }
        __syncthreads();

        uint32_t khb = sb + 2*QSM + (t & 1) * KVST;
        uint32_t klb = khb + PLANE;
        uint32_t vhb = khb + 2*PLANE;
        uint32_t vlb = khb + 3*PLANE;

        float sc[8][4];
        #pragma unroll
        for (int nf = 0; nf < 8; nf++)
            #pragma unroll
            for (int v = 0; v < 4; v++) sc[nf][v] = 0.0f;

        #pragma unroll
        for (int kc = 0; kc < 4; kc++) {
            uint32_t qoff = (uint32_t)(wid*16 + lr) * ROWB + (kc*16 + lk) * 2;
            uint32_t qh[4], ql[4];
            LDMATRIX_X4(qh[0], qh[1], qh[2], qh[3], sb + qoff);
            LDMATRIX_X4(ql[0], ql[1], ql[2], ql[3], sb + QSM + qoff);
            #pragma unroll
            for (int nb = 0; nb < 4; nb++) {
                uint32_t off = (uint32_t)(nb*16 + lr) * ROWB + (kc*16 + lk) * 2;
                uint32_t bh0, bh1, bh2, bh3, bl0, bl1, bl2, bl3;
                LDMATRIX_X4(bh0, bh1, bh2, bh3, khb + off);
                LDMATRIX_X4(bl0, bl1, bl2, bl3, klb + off);
                MMA_F16(sc[2*nb],   qh, bh0, bh2);
                MMA_F16(sc[2*nb],   ql, bh0, bh2);
                MMA_F16(sc[2*nb],   qh, bl0, bl2);
                MMA_F16(sc[2*nb+1], qh, bh1, bh3);
                MMA_F16(sc[2*nb+1], ql, bh1, bh3);
                MMA_F16(sc[2*nb+1], qh, bl1, bl3);
            }
        }

        if (k0 + 63 > wminrow) {
            int row0 = wminrow + rq;
            #pragma unroll
            for (int nf = 0; nf < 8; nf++) {
                int col = k0 + nf*8 + cq;
                if (col     > row0)     sc[nf][0] = -1e30f;
                if (col + 1 > row0)     sc[nf][1] = -1e30f;
                if (col     > row0 + 8) sc[nf][2] = -1e30f;
                if (col + 1 > row0 + 8) sc[nf][3] = -1e30f;
            }
        }

        uint32_t pr[8][2];
        #pragma unroll
        for (int i = 0; i < 2; i++) {
            float mx = -1e30f;
            #pragma unroll
            for (int nf = 0; nf < 8; nf++)
                mx = fmaxf(mx, fmaxf(sc[nf][2*i], sc[nf][2*i+1]));
            mx = fmaxf(mx, __shfl_xor_sync(0xffffffffu, mx, 1));
            mx = fmaxf(mx, __shfl_xor_sync(0xffffffffu, mx, 2));
            float mnew  = fmaxf(m_i[i], mx);
            float scale = ex2f(m_i[i] - mnew);
            float neg   = -mnew;
            #pragma unroll
            for (int nf = 0; nf < 8; nf++) {
                float p0 = ex2f(sc[nf][2*i]   + neg);
                float p1 = ex2f(sc[nf][2*i+1] + neg);
                asm("cvt.rn.f16x2.f32 %0, %1, %2;" : "=r"(pr[nf][i]) : "f"(p1), "f"(p0));
            }
            m_i[i] = mnew;
            lacc[2*i]   *= scale;
            lacc[2*i+1] *= scale;
            #pragma unroll
            for (int nf = 0; nf < 8; nf++) {
                acc[nf][2*i]   *= scale;
                acc[nf][2*i+1] *= scale;
            }
        }

        #pragma unroll
        for (int kc = 0; kc < 4; kc++) {
            uint32_t ph[4] = { pr[2*kc][0], pr[2*kc][1], pr[2*kc+1][0], pr[2*kc+1][1] };
            MMA_F16(lacc, ph, 0x3C003C00u, 0x3C003C00u);
            #pragma unroll
            for (int db = 0; db < 4; db++) {
                uint32_t off = (uint32_t)(kc*16 + (lane & 15)) * ROWB
                             + (db*16 + ((lane >> 4) << 3)) * 2;
                uint32_t vh0, vh1, vh2, vh3, vl0, vl1, vl2, vl3;
                LDMATRIX_X4T(vh0, vh1, vh2, vh3, vhb + off);
                LDMATRIX_X4T(vl0, vl1, vl2, vl3, vlb + off);
                MMA_F16(acc[2*db],   ph, vh0, vh1);
                MMA_F16(acc[2*db],   ph, vl0, vl1);
                MMA_F16(acc[2*db+1], ph, vh2, vh3);
                MMA_F16(acc[2*db+1], ph, vl2, vl3);
            }
        }
        __syncthreads();
    }

    // epilogue: normalize + fp16 hi/lo split straight into g_A3[0]
    int b = bh >> 4, h = bh & 15;
    #pragma unroll
    for (int i = 0; i < 2; i++) {
        float inv = 1.0f / lacc[2*i];
        int s = q0 + wid*16 + rq + 8*i;
        __half* rowp = g_A3 + ((size_t)(b * SEQ + s) << 11) + (h << 6);
        #pragma unroll
        for (int nf = 0; nf < 8; nf++) {
            float v0 = acc[nf][2*i]   * inv;
            float v1 = acc[nf][2*i+1] * inv;
            __half2 hv = __floats2half2_rn(v0, v1);
            __half2 lv = __floats2half2_rn(v0 - __half2float(__low2half(hv)),
                                           v1 - __half2float(__high2half(hv)));
            *(__half2*)(rowp + nf*8 + cq)        = hv;
            *(__half2*)(rowp + 1024 + nf*8 + cq) = lv;
        }
    }
}

// ---------------------------------------------------------------------------
extern "C" void kernel_launch(void* const* d_in, const int* in_sizes, int n_in,
                              void* d_out, int out_size)
{
    const float* query = (const float*)d_in[0];
    const float* key   = (const float*)d_in[1];
    const float* value = (const float*)d_in[2];
    const float* w_q = (const float*)d_in[4];
    const float* b_q = (const float*)d_in[5];
    const float* w_k = (const float*)d_in[6];
    const float* b_k = (const float*)d_in[7];
    const float* w_v = (const float*)d_in[8];
    const float* b_v = (const float*)d_in[9];
    const float* w_o = (const float*)d_in[10];
    const float* b_o = (const float*)d_in[11];
    float* out = (float*)d_out;

    static int attr_set = 0;
    if (!attr_set) {
        cudaFuncSetAttribute(gemm_mma, cudaFuncAttributeMaxDynamicSharedMemorySize, GEMM_SMEM);
        cudaFuncSetAttribute(attn_mma, cudaFuncAttributeMaxDynamicSharedMemorySize, ATTN_SMEM);
        attr_set = 1;
    }

    // 0: all three X splits (one launch, z = q/k/v)
    split_x3<<<dim3(MROWS, 1, 3), 256>>>(query, key, value);
    // 1: all three weight converts
    split_w3<<<dim3(DIM, 1, 3), 256>>>(w_q, w_k, w_v);
    // 2: output-projection weight
    split_wo<<<DIM, 256>>>(w_o);
    // 3: fused QKV GEMM (profiled)
    gemm_mma<<<dim3(DIM/128, MROWS/128, 3), 256, GEMM_SMEM>>>(b_q, b_k, b_v, nullptr, 0);
    // 4: RoPE tables
    init_tbl<<<SEQ*32/256, 256>>>();
    // 5: RoPE + fp16 conversion
    conv_rope<<<dim3(BATCH*NH*SEQ/8, 3), 256>>>();
    // 6: attention (ctx -> g_A3[0])
    attn_mma<<<dim3(SEQ/128, BATCH*NH), 256, ATTN_SMEM>>>();
    // 7: output projection
    gemm_mma<<<dim3(DIM/128, MROWS/128, 1), 256, GEMM_SMEM>>>(b_o, nullptr, nullptr, out, 1);
}

// round 14
// speedup vs baseline: 2.4130x; 1.0045x over previous
#include <cuda_runtime.h>
#include <cuda_fp16.h>
#include <math.h>
#include <stdint.h>

#define BATCH 4
#define SEQ   2048
#define DIM   1024
#define NH    16
#define HD    64
#define MROWS (BATCH*SEQ)
#define ASZ   ((size_t)MROWS*2048)

// ---------------------------------------------------------------------------
// Scratch (__device__ globals; allocation-free rule)
// ---------------------------------------------------------------------------
// fp16x2 GEMM A operands: 3 buffers of [Xhi | Xlo] rows (width 2048).
// Buffer 0 doubles as the attention-context buffer for the o-projection.
__device__ __half g_A3[3*ASZ];
// fp16 weights: g_B2 = concat [Wq; Wk; Wv], g_B2o = Wo
__device__ __half g_B2[(size_t)3*DIM*DIM];
__device__ __half g_B2o[(size_t)DIM*DIM];
// fp16 hi/lo planes for attention (RoPE + scale pre-applied to Q/K)
__device__ __half g_Qh[BATCH*NH*SEQ*HD];
__device__ __half g_Ql[BATCH*NH*SEQ*HD];
__device__ __half g_Kh[BATCH*NH*SEQ*HD];
__device__ __half g_Kl[BATCH*NH*SEQ*HD];
__device__ __half g_Vh[BATCH*NH*SEQ*HD];
__device__ __half g_Vl[BATCH*NH*SEQ*HD];
// RoPE tables
__device__ float g_costab[SEQ*32];
__device__ float g_sintab[SEQ*32];

__device__ __forceinline__ uint32_t smem_u32(const void* p) {
    uint32_t a;
    asm("{ .reg .u64 t; cvta.to.shared.u64 t, %1; cvt.u32.u64 %0, t; }" : "=r"(a) : "l"(p));
    return a;
}

#define LDMATRIX_X4(r0, r1, r2, r3, addr) \
    asm volatile("ldmatrix.sync.aligned.m8n8.x4.shared.b16 {%0,%1,%2,%3}, [%4];" \
        : "=r"(r0), "=r"(r1), "=r"(r2), "=r"(r3) : "r"(addr))

#define LDMATRIX_X4T(r0, r1, r2, r3, addr) \
    asm volatile("ldmatrix.sync.aligned.m8n8.x4.trans.shared.b16 {%0,%1,%2,%3}, [%4];" \
        : "=r"(r0), "=r"(r1), "=r"(r2), "=r"(r3) : "r"(addr))

#define MMA_F16(c, a, b0v, b1v) \
    asm volatile("mma.sync.aligned.m16n8k16.row.col.f32.f16.f16.f32 " \
        "{%0,%1,%2,%3}, {%4,%5,%6,%7}, {%8,%9}, {%0,%1,%2,%3};" \
        : "+f"((c)[0]), "+f"((c)[1]), "+f"((c)[2]), "+f"((c)[3]) \
        : "r"((a)[0]), "r"((a)[1]), "r"((a)[2]), "r"((a)[3]), "r"(b0v), "r"(b1v))

#define CP_ASYNC16(dst, src) \
    asm volatile("cp.async.cg.shared.global [%0], [%1], 16;" :: "r"(dst), "l"(src))
#define CP_COMMIT() asm volatile("cp.async.commit_group;" ::: "memory")
#define CP_WAIT0()  asm volatile("cp.async.wait_group 0;" ::: "memory")
#define CP_WAIT1()  asm volatile("cp.async.wait_group 1;" ::: "memory")

__device__ __forceinline__ uint32_t h2u(__half2 h) { return *reinterpret_cast<uint32_t*>(&h); }
__device__ __forceinline__ float ex2f(float x) {
    float y; asm("ex2.approx.f32 %0, %1;" : "=f"(y) : "f"(x)); return y;
}

struct h4 { __half2 a, b; };

#define QSCALE 0.18033688011112042f   // 0.125 * log2(e)

// ---------------------------------------------------------------------------
// RoPE table init (65536 pow/sincos total, bit-identical to reference math)
// ---------------------------------------------------------------------------
__global__ void init_tbl()
{
    int idx = blockIdx.x * blockDim.x + threadIdx.x;
    if (idx >= SEQ * 32) return;
    int lane = idx & 31;
    int s    = idx >> 5;
    float invf = (float)pow(10000.0, -(double)lane / 32.0);
    float sn, cs;
    sincosf((float)s * invf, &sn, &cs);
    g_costab[idx] = cs;
    g_sintab[idx] = sn;
}

// ---------------------------------------------------------------------------
// X split x3: f32 -> fp16 hi/lo into g_A3[z]  (z = blockIdx.z: 0=q,1=k,2=v)
// ---------------------------------------------------------------------------
__global__ void split_x3(const float* __restrict__ q, const float* __restrict__ k,
                         const float* __restrict__ v)
{
    int z = blockIdx.z;
    const float* src = (z == 0) ? q : (z == 1) ? k : v;
    int i = blockIdx.x * blockDim.x + threadIdx.x;
    if (i >= MROWS * 256) return;
    int r = i >> 8, c4 = i & 255;
    float4 vv = ((const float4*)src)[i];
    __half2 h01 = __floats2half2_rn(vv.x, vv.y);
    __half2 h23 = __floats2half2_rn(vv.z, vv.w);
    __half2 l01 = __floats2half2_rn(vv.x - __half2float(__low2half(h01)),
                                    vv.y - __half2float(__high2half(h01)));
    __half2 l23 = __floats2half2_rn(vv.z - __half2float(__low2half(h23)),
                                    vv.w - __half2float(__high2half(h23)));
    __half* out = g_A3 + (size_t)z * ASZ;
    size_t base = (size_t)r * 2048 + c4 * 4;
    h4 hv; hv.a = h01; hv.b = h23;
    h4 lv; lv.a = l01; lv.b = l23;
    *(h4*)(out + base)        = hv;
    *(h4*)(out + base + 1024) = lv;
}

// ---------------------------------------------------------------------------
// W convert x3 + Wo
// ---------------------------------------------------------------------------
__global__ void split_w3(const float* __restrict__ wq, const float* __restrict__ wk,
                         const float* __restrict__ wv)
{
    int z = blockIdx.z;
    const float* src = (z == 0) ? wq : (z == 1) ? wk : wv;
    int i = blockIdx.x * blockDim.x + threadIdx.x;
    if (i >= DIM * 256) return;
    float4 v = ((const float4*)src)[i];
    h4 hv;
    hv.a = __floats2half2_rn(v.x, v.y);
    hv.b = __floats2half2_rn(v.z, v.w);
    *(h4*)(g_B2 + (size_t)z * DIM * DIM + (size_t)i * 4) = hv;
}

__global__ void split_wo(const float* __restrict__ in)
{
    int i = blockIdx.x * blockDim.x + threadIdx.x;
    if (i >= DIM * 256) return;
    float4 v = ((const float4*)in)[i];
    h4 hv;
    hv.a = __floats2half2_rn(v.x, v.y);
    hv.b = __floats2half2_rn(v.z, v.w);
    *(h4*)(g_B2o + (size_t)i * 4) = hv;
}

// ---------------------------------------------------------------------------
// mma.sync fp16x2 GEMM, 3-stage cp.async pipeline, fused-QKV.
// opro=0 (gridDim.z=3): epilogue stages tile to smem, applies table-RoPE +
//   QSCALE (z=0), plain (z=2), and writes fp16 hi/lo head-major planes.
// opro=1: A=g_A3[0] (ctx), B=g_B2o, f32 row-major dst (d_out).
// ---------------------------------------------------------------------------
#define NST      32
#define STAGE_B  (128*144)
#define GEMM_SMEM (6*STAGE_B)            // 110592
#define EPF      136                     // epilogue f32 pitch (floats)

__global__ __launch_bounds__(256)
void gemm_mma(const float* __restrict__ b0, const float* __restrict__ b1,
              const float* __restrict__ b2, float* __restrict__ dst_param,
              int opro)
{
    extern __shared__ __align__(16) char sm[];
    uint32_t sb = smem_u32(sm);

    int z = blockIdx.z;
    const float* bias = opro ? b0 : (z == 0) ? b0 : (z == 1) ? b1 : b2;
    const __half* Amat = g_A3 + (opro ? 0 : (size_t)z * ASZ);
    const __half* Bmat = opro ? g_B2o : g_B2 + (size_t)z * DIM * DIM;

    int tid  = threadIdx.x;
    int lane = tid & 31;
    int wid  = tid >> 5;
    int wm   = wid & 1;
    int wn   = wid >> 1;
    int m0 = blockIdx.y << 7, n0 = blockIdx.x << 7;

    int lr = ((lane >> 3) & 1) * 8 + (lane & 7);
    int lk = (lane >> 4) * 8;

    float c[4][4][4];
    #pragma unroll
    for (int mf = 0; mf < 4; mf++)
        #pragma unroll
        for (int nf = 0; nf < 4; nf++)
            #pragma unroll
            for (int v = 0; v < 4; v++) c[mf][nf][v] = 0.0f;

    auto load_stage = [&](int t, int buf) {
        int kp = t << 6;
        int bc = kp & 1023;
        const __half* Ab = Amat + (size_t)m0 * 2048 + kp;
        const __half* Bb = Bmat + (size_t)n0 * 1024 + bc;
        uint32_t sa  = sb + buf * STAGE_B;
        uint32_t sbb = sb + 3 * STAGE_B + buf * STAGE_B;
        #pragma unroll
        for (int it = 0; it < 4; it++) {
            int id = tid + (it << 8);
            int r = id >> 3, ch = id & 7;
            CP_ASYNC16(sa  + r * 144 + (ch << 4), Ab + (size_t)r * 2048 + (ch << 3));
            CP_ASYNC16(sbb + r * 144 + (ch << 4), Bb + (size_t)r * 1024 + (ch << 3));
        }
        CP_COMMIT();
    };

    load_stage(0, 0);
    load_stage(1, 1);

    #pragma unroll 1
    for (int t = 0; t < NST; t++) {
        if (t + 1 < NST) { CP_WAIT1(); } else { CP_WAIT0(); }
        __syncthreads();
        if (t + 2 < NST) load_stage(t + 2, (t + 2) % 3);

        int buf = t % 3;
        uint32_t sa  = sb + buf * STAGE_B;
        uint32_t sbb = sb + 3 * STAGE_B + buf * STAGE_B;

        #pragma unroll
        for (int kk = 0; kk < 64; kk += 16) {
            uint32_t a[4][4];
            #pragma unroll
            for (int mf = 0; mf < 4; mf++) {
                uint32_t ad = sa + (uint32_t)(wm * 64 + mf * 16 + lr) * 144 + (kk + lk) * 2;
                LDMATRIX_X4(a[mf][0], a[mf][1], a[mf][2], a[mf][3], ad);
            }
            uint32_t b[2][4];
            #pragma unroll
            for (int nb = 0; nb < 2; nb++) {
                uint32_t bd = sbb + (uint32_t)(wn * 32 + nb * 16 + lr) * 144 + (kk + lk) * 2;
                LDMATRIX_X4(b[nb][0], b[nb][1], b[nb][2], b[nb][3], bd);
            }
            #pragma unroll
            for (int mf = 0; mf < 4; mf++) {
                #pragma unroll
                for (int nf = 0; nf < 4; nf++) {
                    int nb = nf >> 1;
                    uint32_t bb0 = (nf & 1) ? b[nb][1] : b[nb][0];
                    uint32_t bb1 = (nf & 1) ? b[nb][3] : b[nb][2];
                    MMA_F16(c[mf][nf], a[mf], bb0, bb1);
                }
            }
        }
        __syncthreads();
    }

    int rq = lane >> 2, cq = (lane & 3) * 2;
    float2 bv[4];
    #pragma unroll
    for (int nf = 0; nf < 4; nf++) {
        int col = n0 + wn * 32 + nf * 8 + cq;
        bv[nf] = make_float2(bias[col], bias[col + 1]);
    }

    if (opro) {
        #pragma unroll
        for (int mf = 0; mf < 4; mf++) {
            #pragma unroll
            for (int nf = 0; nf < 4; nf++) {
                int r   = m0 + wm * 64 + mf * 16 + rq;
                int col = n0 + wn * 32 + nf * 8 + cq;
                float2 lo = make_float2(c[mf][nf][0] + bv[nf].x, c[mf][nf][1] + bv[nf].y);
                float2 hi = make_float2(c[mf][nf][2] + bv[nf].x, c[mf][nf][3] + bv[nf].y);
                *(float2*)(dst_param + (size_t)r * 1024 + col)       = lo;
                *(float2*)(dst_param + (size_t)(r + 8) * 1024 + col) = hi;
            }
        }
        return;
    }

    // ---- fused RoPE + fp16 hi/lo epilogue (z = 0:Q, 1:K, 2:V) ----
    float* st = (float*)sm;   // 128 x EPF floats (69632 B)
    #pragma unroll
    for (int mf = 0; mf < 4; mf++) {
        #pragma unroll
        for (int nf = 0; nf < 4; nf++) {
            int r   = wm * 64 + mf * 16 + rq;
            int col = wn * 32 + nf * 8 + cq;
            *(float2*)&st[r * EPF + col] =
                make_float2(c[mf][nf][0] + bv[nf].x, c[mf][nf][1] + bv[nf].y);
            *(float2*)&st[(r + 8) * EPF + col] =
                make_float2(c[mf][nf][2] + bv[nf].x, c[mf][nf][3] + bv[nf].y);
        }
    }
    __syncthreads();

    int row = tid >> 1;            // 0..127
    int hsel = tid & 1;            // head half within the 128-col tile
    int m = m0 + row;
    int b = m >> 11, s = m & 2047;
    int h = (n0 >> 6) + hsel;

    float x[64];
    const float* xr = st + row * EPF + hsel * 64;
    #pragma unroll
    for (int i = 0; i < 16; i++)
        *(float4*)&x[i * 4] = *(const float4*)&xr[i * 4];

    __half* dh = (z == 0) ? g_Qh : (z == 1) ? g_Kh : g_Vh;
    __half* dl = (z == 0) ? g_Ql : (z == 1) ? g_Kl : g_Vl;
    size_t off = ((size_t)(b * NH + h) * SEQ + s) << 6;

    #pragma unroll
    for (int g = 0; g < 4; g++) {
        float v0[8], v1[8];
        if (z < 2) {
            #pragma unroll
            for (int j = 0; j < 8; j++) {
                int d = g * 8 + j;
                float cs = g_costab[(s << 5) + d];
                float sn = g_sintab[(s << 5) + d];
                v0[j] = x[d]      * cs - x[2*d + 1] * sn;
                v1[j] = x[d + 32] * cs + x[2*d]     * sn;
                if (z == 0) { v0[j] *= QSCALE; v1[j] *= QSCALE; }
            }
        } else {
            #pragma unroll
            for (int j = 0; j < 8; j++) {
                int d = g * 8 + j;
                v0[j] = x[d];
                v1[j] = x[d + 32];
            }
        }
        uint4 h0v, l0v, h1v, l1v;
        uint32_t* h0p = (uint32_t*)&h0v; uint32_t* l0p = (uint32_t*)&l0v;
        uint32_t* h1p = (uint32_t*)&h1v; uint32_t* l1p = (uint32_t*)&l1v;
        #pragma unroll
        for (int p = 0; p < 4; p++) {
            __half2 hh0 = __floats2half2_rn(v0[2*p], v0[2*p+1]);
            __half2 ll0 = __floats2half2_rn(v0[2*p]   - __half2float(__low2half(hh0)),
                                            v0[2*p+1] - __half2float(__high2half(hh0)));
            h0p[p] = h2u(hh0); l0p[p] = h2u(ll0);
            __half2 hh1 = __floats2half2_rn(v1[2*p], v1[2*p+1]);
            __half2 ll1 = __floats2half2_rn(v1[2*p]   - __half2float(__low2half(hh1)),
                                            v1[2*p+1] - __half2float(__high2half(hh1)));
            h1p[p] = h2u(hh1); l1p[p] = h2u(ll1);
        }
        *(uint4*)(dh + off + g * 8)      = h0v;
        *(uint4*)(dh + off + 32 + g * 8) = h1v;
        *(uint4*)(dl + off + g * 8)      = l0v;
        *(uint4*)(dl + off + 32 + g * 8) = l1v;
    }
}

// ---------------------------------------------------------------------------
// Flash attention (R11+ version, unchanged): BM=128 (8 warps), BN=64,
// Q in SMEM, launch_bounds(256,2), f32 ex2 softmax, ones-MMA sums.
// Epilogue writes fp16 hi/lo ctx into g_A3[0] for the o-projection.
// ---------------------------------------------------------------------------
#define ROWB 144
#define QSM  18432
#define PLANE (64*ROWB)
#define KVST (4*PLANE)
#define ATTN_SMEM (2*QSM + 2*KVST)   // 110592

__global__ __launch_bounds__(256, 2)
void attn_mma()
{
    extern __shared__ __align__(16) char smb[];
    uint32_t sb = smem_u32(smb);

    int tid  = threadIdx.x;
    int lane = tid & 31;
    int wid  = tid >> 5;
    int bh   = blockIdx.y;
    int bx   = gridDim.x - 1 - blockIdx.x;
    int q0   = bx << 7;
    int nt   = 2 * bx + 2;

    const __half* Kh = g_Kh + (size_t)bh * SEQ * HD;
    const __half* Kl = g_Kl + (size_t)bh * SEQ * HD;
    const __half* Vh = g_Vh + (size_t)bh * SEQ * HD;
    const __half* Vl = g_Vl + (size_t)bh * SEQ * HD;

    int lr = ((lane >> 3) & 1) * 8 + (lane & 7);
    int lk = (lane >> 4) * 8;
    int rq = lane >> 2, cq = (lane & 3) * 2;

    auto load_kv = [&](int t, int stage) {
        int k0 = t << 6;
        uint32_t base = sb + 2*QSM + stage * KVST;
        #pragma unroll
        for (int it = 0; it < 2; it++) {
            int id = tid + (it << 8);
            int r = id >> 3, ch = id & 7;
            uint32_t o = r * ROWB + (ch << 4);
            int go = ((k0 + r) << 6) + (ch << 3);
            CP_ASYNC16(base + o,             Kh + go);
            CP_ASYNC16(base + PLANE + o,     Kl + go);
            CP_ASYNC16(base + 2*PLANE + o,   Vh + go);
            CP_ASYNC16(base + 3*PLANE + o,   Vl + go);
        }
        CP_COMMIT();
    };

    {
        const __half* Qh = g_Qh + (size_t)bh * SEQ * HD;
        const __half* Ql = g_Ql + (size_t)bh * SEQ * HD;
        #pragma unroll
        for (int it = 0; it < 8; it++) {
            int id = tid + (it << 8);
            int pl = id >> 10;
            int rem = id & 1023;
            int r = rem >> 3, ch = rem & 7;
            uint32_t o = pl * QSM + r * ROWB + (ch << 4);
            const __half* src = pl ? Ql : Qh;
            CP_ASYNC16(sb + o, src + ((q0 + r) << 6) + (ch << 3));
        }
        CP_COMMIT();
    }
    load_kv(0, 0);

    float acc[8][4];
    #pragma unroll
    for (int nf = 0; nf < 8; nf++)
        #pragma unroll
        for (int v = 0; v < 4; v++) acc[nf][v] = 0.0f;
    float lacc[4] = {0.0f, 0.0f, 0.0f, 0.0f};
    float m_i[2] = {-1e30f, -1e30f};

    int wminrow = q0 + wid*16;

    CP_WAIT0();
    __syncthreads();

    #pragma unroll 1
    for (int t = 0; t < nt; t++) {
        int k0 = t << 6;
        if (t + 1 < nt) { load_kv(t + 1, (t + 1) & 1); CP_WAIT1(); }
        __syncthreads();

        uint32_t khb = sb + 2*QSM + (t & 1) * KVST;
        uint32_t klb = khb + PLANE;
        uint32_t vhb = khb + 2*PLANE;
        uint32_t vlb = khb + 3*PLANE;

        float sc[8][4];
        #pragma unroll
        for (int nf = 0; nf < 8; nf++)
            #pragma unroll
            for (int v = 0; v < 4; v++) sc[nf][v] = 0.0f;

        #pragma unroll
        for (int kc = 0; kc < 4; kc++) {
            uint32_t qoff = (uint32_t)(wid*16 + lr) * ROWB + (kc*16 + lk) * 2;
            uint32_t qh[4], ql[4];
            LDMATRIX_X4(qh[0], qh[1], qh[2], qh[3], sb + qoff);
            LDMATRIX_X4(ql[0], ql[1], ql[2], ql[3], sb + QSM + qoff);
            #pragma unroll
            for (int nb = 0; nb < 4; nb++) {
                uint32_t off = (uint32_t)(nb*16 + lr) * ROWB + (kc*16 + lk) * 2;
                uint32_t bh0, bh1, bh2, bh3, bl0, bl1, bl2, bl3;
                LDMATRIX_X4(bh0, bh1, bh2, bh3, khb + off);
                LDMATRIX_X4(bl0, bl1, bl2, bl3, klb + off);
                MMA_F16(sc[2*nb],   qh, bh0, bh2);
                MMA_F16(sc[2*nb],   ql, bh0, bh2);
                MMA_F16(sc[2*nb],   qh, bl0, bl2);
                MMA_F16(sc[2*nb+1], qh, bh1, bh3);
                MMA_F16(sc[2*nb+1], ql, bh1, bh3);
                MMA_F16(sc[2*nb+1], qh, bl1, bl3);
            }
        }

        if (k0 + 63 > wminrow) {
            int row0 = wminrow + rq;
            #pragma unroll
            for (int nf = 0; nf < 8; nf++) {
                int col = k0 + nf*8 + cq;
                if (col     > row0)     sc[nf][0] = -1e30f;
                if (col + 1 > row0)     sc[nf][1] = -1e30f;
                if (col     > row0 + 8) sc[nf][2] = -1e30f;
                if (col + 1 > row0 + 8) sc[nf][3] = -1e30f;
            }
        }

        uint32_t pr[8][2];
        #pragma unroll
        for (int i = 0; i < 2; i++) {
            float mx = -1e30f;
            #pragma unroll
            for (int nf = 0; nf < 8; nf++)
                mx = fmaxf(mx, fmaxf(sc[nf][2*i], sc[nf][2*i+1]));
            mx = fmaxf(mx, __shfl_xor_sync(0xffffffffu, mx, 1));
            mx = fmaxf(mx, __shfl_xor_sync(0xffffffffu, mx, 2));
            float mnew  = fmaxf(m_i[i], mx);
            float scale = ex2f(m_i[i] - mnew);
            float neg   = -mnew;
            #pragma unroll
            for (int nf = 0; nf < 8; nf++) {
                float p0 = ex2f(sc[nf][2*i]   + neg);
                float p1 = ex2f(sc[nf][2*i+1] + neg);
                asm("cvt.rn.f16x2.f32 %0, %1, %2;" : "=r"(pr[nf][i]) : "f"(p1), "f"(p0));
            }
            m_i[i] = mnew;
            lacc[2*i]   *= scale;
            lacc[2*i+1] *= scale;
            #pragma unroll
            for (int nf = 0; nf < 8; nf++) {
                acc[nf][2*i]   *= scale;
                acc[nf][2*i+1] *= scale;
            }
        }

        #pragma unroll
        for (int kc = 0; kc < 4; kc++) {
            uint32_t ph[4] = { pr[2*kc][0], pr[2*kc][1], pr[2*kc+1][0], pr[2*kc+1][1] };
            MMA_F16(lacc, ph, 0x3C003C00u, 0x3C003C00u);
            #pragma unroll
            for (int db = 0; db < 4; db++) {
                uint32_t off = (uint32_t)(kc*16 + (lane & 15)) * ROWB
                             + (db*16 + ((lane >> 4) << 3)) * 2;
                uint32_t vh0, vh1, vh2, vh3, vl0, vl1, vl2, vl3;
                LDMATRIX_X4T(vh0, vh1, vh2, vh3, vhb + off);
                LDMATRIX_X4T(vl0, vl1, vl2, vl3, vlb + off);
                MMA_F16(acc[2*db],   ph, vh0, vh1);
                MMA_F16(acc[2*db],   ph, vl0, vl1);
                MMA_F16(acc[2*db+1], ph, vh2, vh3);
                MMA_F16(acc[2*db+1], ph, vl2, vl3);
            }
        }
        __syncthreads();
    }

    int b = bh >> 4, h = bh & 15;
    #pragma unroll
    for (int i = 0; i < 2; i++) {
        float inv = 1.0f / lacc[2*i];
        int s = q0 + wid*16 + rq + 8*i;
        __half* rowp = g_A3 + ((size_t)(b * SEQ + s) << 11) + (h << 6);
        #pragma unroll
        for (int nf = 0; nf < 8; nf++) {
            float v0 = acc[nf][2*i]   * inv;
            float v1 = acc[nf][2*i+1] * inv;
            __half2 hv = __floats2half2_rn(v0, v1);
            __half2 lv = __floats2half2_rn(v0 - __half2float(__low2half(hv)),
                                           v1 - __half2float(__high2half(hv)));
            *(__half2*)(rowp + nf*8 + cq)        = hv;
            *(__half2*)(rowp + 1024 + nf*8 + cq) = lv;
        }
    }
}

// ---------------------------------------------------------------------------
extern "C" void kernel_launch(void* const* d_in, const int* in_sizes, int n_in,
                              void* d_out, int out_size)
{
    const float* query = (const float*)d_in[0];
    const float* key   = (const float*)d_in[1];
    const float* value = (const float*)d_in[2];
    const float* w_q = (const float*)d_in[4];
    const float* b_q = (const float*)d_in[5];
    const float* w_k = (const float*)d_in[6];
    const float* b_k = (const float*)d_in[7];
    const float* w_v = (const float*)d_in[8];
    const float* b_v = (const float*)d_in[9];
    const float* w_o = (const float*)d_in[10];
    const float* b_o = (const float*)d_in[11];
    float* out = (float*)d_out;

    static int attr_set = 0;
    if (!attr_set) {
        cudaFuncSetAttribute(gemm_mma, cudaFuncAttributeMaxDynamicSharedMemorySize, GEMM_SMEM);
        cudaFuncSetAttribute(attn_mma, cudaFuncAttributeMaxDynamicSharedMemorySize, ATTN_SMEM);
        attr_set = 1;
    }

    // 0: RoPE tables (needed by QKV GEMM epilogue)
    init_tbl<<<SEQ*32/256, 256>>>();
    // 1: X splits
    split_x3<<<dim3(MROWS, 1, 3), 256>>>(query, key, value);
    // 2: QKV weights
    split_w3<<<dim3(DIM, 1, 3), 256>>>(w_q, w_k, w_v);
    // 3: fused QKV GEMM + RoPE + fp16 split epilogue (profiled)
    gemm_mma<<<dim3(DIM/128, MROWS/128, 3), 256, GEMM_SMEM>>>(b_q, b_k, b_v, nullptr, 0);
    // 4: o-proj weight
    split_wo<<<DIM, 256>>>(w_o);
    // 5: attention (ctx -> g_A3[0])
    attn_mma<<<dim3(SEQ/128, BATCH*NH), 256, ATTN_SMEM>>>();
    // 6: output projection
    gemm_mma<<<dim3(DIM/128, MROWS/128, 1), 256, GEMM_SMEM>>>(b_o, nullptr, nullptr, out, 1);
}